// round 12
// baseline (speedup 1.0000x reference)
#include <cuda_runtime.h>
#include <cstdint>

#define DEV_INLINE __device__ __forceinline__

// Problem constants
constexpr int BATCH = 32;
constexpr int SEQ   = 1024;
constexpr int HD    = 256;
constexpr int MTOT  = BATCH * SEQ;   // 32768

// GEMM tiling (all GEMMs are NT: C[M,N] = A[M,K] @ B[N,K]^T, K-major operands)
// 256 threads / 8 warps (4m x 2n), warp tile 32x64 (R10-proven shape).
constexpr int BM = 128, BN = 128, BK = 16;
constexpr int ST = 20;                    // padded smem row stride (floats)
constexpr int TILE_WORDS = BM * ST;       // 2560 floats per operand tile
constexpr int STAGES = 5;                 // 4 tile-loads in flight
constexpr int STAGE_BYTES = 2 * TILE_WORDS * 4;       // A+B per stage, 20480 B
constexpr int GEMM_SMEM = STAGES * STAGE_BYTES;       // 102400 B dynamic

// ---------------------------------------------------------------------------
// Scratch (device globals: the sanctioned no-alloc path)
// ---------------------------------------------------------------------------
__device__ float g_Q [(size_t)MTOT * HD];
__device__ float g_K [(size_t)MTOT * HD];
__device__ float g_V [(size_t)MTOT * HD];
__device__ float g_VT[(size_t)MTOT * HD];           // per-batch transposed V (tf32)
__device__ float g_O [(size_t)MTOT * HD];
__device__ float g_X1[(size_t)MTOT * HD];
__device__ float g_T1[(size_t)MTOT * HD];
__device__ float g_T2[(size_t)MTOT * HD];
__device__ float g_F [(size_t)MTOT * HD];           // rounded features
__device__ float g_S [(size_t)BATCH * SEQ * SEQ];   // 128 MB: exp(scores), tf32
__device__ float g_P [(size_t)BATCH * 8 * SEQ];     // per n-tile partial row sums
__device__ float g_Ri[(size_t)BATCH * SEQ];         // 1 / rowsum
__device__ float g_WR[(size_t)5 * 3 * HD * HD];     // rounded weights (q,k,v,ca,l)

// ---------------------------------------------------------------------------
// Helpers
// ---------------------------------------------------------------------------
DEV_INLINE float to_tf32(float x) {
    unsigned u;
    asm("cvt.rna.tf32.f32 %0, %1;" : "=r"(u) : "f"(x));
    return __uint_as_float(u);
}

DEV_INLINE void mma_tf32(float c[4], const unsigned a[4], const unsigned b[2]) {
    asm volatile(
        "mma.sync.aligned.m16n8k8.row.col.f32.tf32.tf32.f32 "
        "{%0,%1,%2,%3}, {%4,%5,%6,%7}, {%8,%9}, {%0,%1,%2,%3};"
        : "+f"(c[0]), "+f"(c[1]), "+f"(c[2]), "+f"(c[3])
        : "r"(a[0]), "r"(a[1]), "r"(a[2]), "r"(a[3]), "r"(b[0]), "r"(b[1]));
}

DEV_INLINE void ldsm4(uint32_t addr, unsigned& r0, unsigned& r1,
                      unsigned& r2, unsigned& r3) {
    asm volatile("ldmatrix.sync.aligned.m8n8.x4.shared.b16 {%0,%1,%2,%3}, [%4];"
                 : "=r"(r0), "=r"(r1), "=r"(r2), "=r"(r3) : "r"(addr));
}

DEV_INLINE uint32_t smem_u32(const void* p) {
    uint32_t a;
    asm("{ .reg .u64 t; cvta.to.shared.u64 t, %1; cvt.u32.u64 %0, t; }" : "=r"(a) : "l"(p));
    return a;
}

DEV_INLINE void cp16(uint32_t dst, const void* src) {
    asm volatile("cp.async.cg.shared.global [%0], [%1], 16;"
                 :: "r"(dst), "l"(src) : "memory");
}

DEV_INLINE float wsum(float v) {
    #pragma unroll
    for (int o = 16; o; o >>= 1) v += __shfl_xor_sync(0xffffffffu, v, o);
    return v;
}

// ---------------------------------------------------------------------------
// Shared GEMM body: tf32 NT, cp.async 5-stage BK=16 pipeline, ldmatrix frags.
// 256 threads, 8 warps (4m x 2n), warp tile 32x64.
// ALL global operands must already be tf32-rounded.
//   EPI 0: C = A@B^T + bias[col]; roundOut!=0 -> tf32-round stores
//   EPI 1: scores: store tf32(exp(scale*s + shift-inv mask bias)), row partials
//   EPI 3: C = (A@B^T) * aux[row]
// ---------------------------------------------------------------------------
template<int EPI>
DEV_INLINE void gemm_body(
    const float* __restrict__ A, const float* __restrict__ B,
    const float* __restrict__ auxp, float* __restrict__ C,
    int Kdim, int ldA, int ldB, int ldC,
    int m0, int n0, float* __restrict__ PpartDst, int roundOut)
{
    extern __shared__ float smem[];
    const uint32_t sbase = smem_u32(smem);

    const int tid  = threadIdx.x;
    const int warp = tid >> 5, lane = tid & 31;
    const int wm = warp >> 1, wn = warp & 1;
    const int gr = lane >> 2, tig = lane & 3;

    float acc[2][8][4];
    #pragma unroll
    for (int t = 0; t < 2; t++)
        #pragma unroll
        for (int j = 0; j < 8; j++)
            #pragma unroll
            for (int q = 0; q < 4; q++) acc[t][j][q] = 0.f;

    // copy indices: thread -> rows ar, ar+64; k cols ac..ac+3 (16B each)
    const int ar = tid >> 2;
    const int ac = (tid & 3) * 4;
    const float* gA0 = A + (size_t)(m0 + ar) * ldA + ac;
    const float* gA1 = gA0 + (size_t)64 * ldA;
    const float* gB0 = B + (size_t)(n0 + ar) * ldB + ac;
    const float* gB1 = gB0 + (size_t)64 * ldB;
    const uint32_t so = (uint32_t)(ar * ST + ac) * 4;

    // ldmatrix per-lane coordinates (byte offsets, stage-relative)
    const int la_row = lane & 15;
    const int la_k   = (lane >> 4) * 4;
    const int lb_n   = (lane & 7) + ((lane >> 4) << 3);
    const int lb_k   = ((lane >> 3) & 1) * 4;
    const uint32_t aoff0 = (uint32_t)((wm * 32 + la_row) * ST + la_k) * 4;
    const uint32_t aoff1 = aoff0 + 16 * ST * 4;
    uint32_t boff[4];
    #pragma unroll
    for (int jb = 0; jb < 4; jb++)
        boff[jb] = (uint32_t)((wn * 64 + jb * 16 + lb_n) * ST + lb_k) * 4;

    const int KB = Kdim / BK;
    auto issue = [&](int kt, int stg) {
        const uint32_t st = sbase + (uint32_t)stg * STAGE_BYTES;
        const int k0 = kt * BK;
        cp16(st + so, gA0 + k0);
        cp16(st + so + 64 * ST * 4, gA1 + k0);
        cp16(st + TILE_WORDS * 4 + so, gB0 + k0);
        cp16(st + TILE_WORDS * 4 + so + 64 * ST * 4, gB1 + k0);
    };

    // prologue: stages 0..3 (KB >= 8 in all uses)
    issue(0, 0);
    asm volatile("cp.async.commit_group;" ::: "memory");
    issue(1, 1);
    asm volatile("cp.async.commit_group;" ::: "memory");
    issue(2, 2);
    asm volatile("cp.async.commit_group;" ::: "memory");
    issue(3, 3);
    asm volatile("cp.async.commit_group;" ::: "memory");

    int buf = 0;           // stage holding tile kt
    int nstg = 4;          // stage to receive tile kt+STAGES-1
    for (int kt = 0; kt < KB; kt++) {
        asm volatile("cp.async.wait_group %0;" :: "n"(STAGES - 2) : "memory");
        __syncthreads();
        if (kt + STAGES - 1 < KB) issue(kt + STAGES - 1, nstg);
        // ALWAYS commit so the pending-group count stays constant (tail-safe)
        asm volatile("cp.async.commit_group;" ::: "memory");

        const uint32_t stA = sbase + (uint32_t)buf * STAGE_BYTES;
        const uint32_t stB = stA + TILE_WORDS * 4;
        #pragma unroll
        for (int kk = 0; kk < 2; kk++) {
            unsigned af[2][4];
            ldsm4(stA + aoff0 + kk * 32, af[0][0], af[0][1], af[0][2], af[0][3]);
            ldsm4(stA + aoff1 + kk * 32, af[1][0], af[1][1], af[1][2], af[1][3]);
            unsigned bf[4][4];
            #pragma unroll
            for (int jb = 0; jb < 4; jb++)
                ldsm4(stB + boff[jb] + kk * 32,
                      bf[jb][0], bf[jb][1], bf[jb][2], bf[jb][3]);
            #pragma unroll
            for (int j = 0; j < 8; j++) {
                const unsigned* bp = &bf[j >> 1][(j & 1) * 2];
                mma_tf32(acc[0][j], af[0], bp);
                mma_tf32(acc[1][j], af[1], bp);
            }
        }
        buf  = (buf  + 1 == STAGES) ? 0 : buf + 1;
        nstg = (nstg + 1 == STAGES) ? 0 : nstg + 1;
    }

    // Epilogue
    const float SCALE = 0.0625f;  // 1/sqrt(256)
    float rs[2][2];
    rs[0][0] = rs[0][1] = rs[1][0] = rs[1][1] = 0.f;

    #pragma unroll
    for (int t = 0; t < 2; t++) {
        const int r0 = m0 + wm * 32 + t * 16 + gr;
        const int r1 = r0 + 8;
        float mq0 = 0.f, mq1 = 0.f, rv0 = 0.f, rv1 = 0.f;
        if (EPI == 1) { mq0 = auxp[r0]; mq1 = auxp[r1]; }
        if (EPI == 3) { rv0 = auxp[r0]; rv1 = auxp[r1]; }
        #pragma unroll
        for (int j = 0; j < 8; j++) {
            const int c = n0 + wn * 64 + j * 8 + 2 * tig;
            float x0 = acc[t][j][0], x1 = acc[t][j][1];
            float x2 = acc[t][j][2], x3 = acc[t][j][3];
            if (EPI == 0) {
                const float b0 = auxp[c], b1 = auxp[c + 1];
                float y0 = x0 + b0, y1 = x1 + b1;
                float y2 = x2 + b0, y3 = x3 + b1;
                if (roundOut) {
                    y0 = to_tf32(y0); y1 = to_tf32(y1);
                    y2 = to_tf32(y2); y3 = to_tf32(y3);
                }
                float2 v0 = {y0, y1};
                float2 v1 = {y2, y3};
                *(float2*)&C[(size_t)r0 * ldC + c] = v0;
                *(float2*)&C[(size_t)r1 * ldC + c] = v1;
            } else if (EPI == 1) {
                // shift-invariant mask bias: mq ? (mk ? +1 : masked->0) : 0
                const float mc0 = auxp[c], mc1 = auxp[c + 1];
                float e00, e01, e10, e11;
                if (mq0 > 0.5f) {
                    e00 = (mc0 > 0.5f) ? __expf(x0 * SCALE + 1.f) : 0.f;
                    e01 = (mc1 > 0.5f) ? __expf(x1 * SCALE + 1.f) : 0.f;
                } else {
                    e00 = __expf(x0 * SCALE);
                    e01 = __expf(x1 * SCALE);
                }
                if (mq1 > 0.5f) {
                    e10 = (mc0 > 0.5f) ? __expf(x2 * SCALE + 1.f) : 0.f;
                    e11 = (mc1 > 0.5f) ? __expf(x3 * SCALE + 1.f) : 0.f;
                } else {
                    e10 = __expf(x2 * SCALE);
                    e11 = __expf(x3 * SCALE);
                }
                // round first so PV operand and row sum are consistent
                e00 = to_tf32(e00); e01 = to_tf32(e01);
                e10 = to_tf32(e10); e11 = to_tf32(e11);
                rs[t][0] += e00 + e01;
                rs[t][1] += e10 + e11;
                float2 v0 = {e00, e01};
                float2 v1 = {e10, e11};
                *(float2*)&C[(size_t)r0 * ldC + c] = v0;
                *(float2*)&C[(size_t)r1 * ldC + c] = v1;
            } else {
                float2 v0 = {x0 * rv0, x1 * rv0};
                float2 v1 = {x2 * rv1, x3 * rv1};
                *(float2*)&C[(size_t)r0 * ldC + c] = v0;
                *(float2*)&C[(size_t)r1 * ldC + c] = v1;
            }
        }
    }

    if (EPI == 1) {
        asm volatile("cp.async.wait_group 0;" ::: "memory");
        __syncthreads();   // all smem use done before reuse as reduce buffer
        float* part = smem;
        #pragma unroll
        for (int t = 0; t < 2; t++) {
            #pragma unroll
            for (int rr = 0; rr < 2; rr++) {
                float v = rs[t][rr];
                v += __shfl_xor_sync(0xffffffffu, v, 1);
                v += __shfl_xor_sync(0xffffffffu, v, 2);
                if (tig == 0)
                    part[wn * 128 + wm * 32 + t * 16 + rr * 8 + gr] = v;
            }
        }
        __syncthreads();
        if (tid < 128)
            PpartDst[tid] = part[tid] + part[128 + tid];
    }
}

// ---------------------------------------------------------------------------
// Generic batched GEMM wrapper
// ---------------------------------------------------------------------------
template<int EPI>
__global__ void __launch_bounds__(256, 2) gemm_k(
    const float* __restrict__ Ag, const float* __restrict__ Bg,
    const float* __restrict__ aux, float* __restrict__ Cg,
    int Kdim, int ldA, int ldB, int ldC,
    size_t sA, size_t sB, size_t sC, int auxStride,
    float* __restrict__ Ppart, int roundOut)
{
    const int z = blockIdx.z;
    const int m0 = blockIdx.y * BM;
    const int n0 = blockIdx.x * BN;
    float* pdst = (EPI == 1)
        ? Ppart + ((size_t)z * 8 + blockIdx.x) * SEQ + m0 : nullptr;
    gemm_body<EPI>(Ag + (size_t)z * sA, Bg + (size_t)z * sB,
                   aux + (size_t)z * auxStride, Cg + (size_t)z * sC,
                   Kdim, ldA, ldB, ldC, m0, n0, pdst, roundOut);
}

// ---------------------------------------------------------------------------
// 4-way merged projection: Q/K/V/T2 = A @ {qw,kw,vw,lw}^T + bias
// grid (8, 256): blockIdx.x>>1 selects matrix, &1 selects n-half.
// Q,K outputs tf32-rounded (GEMM operands); V,T2 left fp32.
// ---------------------------------------------------------------------------
__global__ void __launch_bounds__(256, 2) proj4_k(
    const float* __restrict__ A,
    const float* __restrict__ w0, const float* __restrict__ w1,
    const float* __restrict__ w2, const float* __restrict__ w3,
    const float* __restrict__ b0, const float* __restrict__ b1,
    const float* __restrict__ b2, const float* __restrict__ b3,
    float* __restrict__ c0, float* __restrict__ c1,
    float* __restrict__ c2, float* __restrict__ c3)
{
    const int g  = blockIdx.x >> 1;
    const int n0 = (blockIdx.x & 1) * BN;
    const int m0 = blockIdx.y * BM;
    const float* W    = (g == 0) ? w0 : (g == 1) ? w1 : (g == 2) ? w2 : w3;
    const float* bias = (g == 0) ? b0 : (g == 1) ? b1 : (g == 2) ? b2 : b3;
    float*       C    = (g == 0) ? c0 : (g == 1) ? c1 : (g == 2) ? c2 : c3;
    gemm_body<0>(A, W, bias, C, HD, HD, HD, HD, m0, n0, nullptr, (g < 2) ? 1 : 0);
}

// ---------------------------------------------------------------------------
// Single-launch tf32 rounding of 5 weight tensors + feats.
// Blocks [0, 5*WB): weights (WB blocks each); [5*WB, 5*WB+FB): feats.
// ---------------------------------------------------------------------------
constexpr int WN = 3 * HD * HD;          // 196608 floats per weight tensor
constexpr int WB = WN / 1024;            // 192 blocks per weight tensor
constexpr int FB = MTOT * HD / 1024;     // 8192 blocks for feats

__global__ void __launch_bounds__(256) round6_k(
    const float* __restrict__ s0, const float* __restrict__ s1,
    const float* __restrict__ s2, const float* __restrict__ s3,
    const float* __restrict__ s4, const float* __restrict__ s5,
    float* __restrict__ d0, float* __restrict__ d1,
    float* __restrict__ d2, float* __restrict__ d3,
    float* __restrict__ d4, float* __restrict__ d5)
{
    const int b = blockIdx.x;
    const float* src; float* dst; int off;
    if (b < 5 * WB) {
        const int seg = b / WB;
        off = (b - seg * WB) * 1024;
        src = (seg == 0) ? s0 : (seg == 1) ? s1 : (seg == 2) ? s2
            : (seg == 3) ? s3 : s4;
        dst = (seg == 0) ? d0 : (seg == 1) ? d1 : (seg == 2) ? d2
            : (seg == 3) ? d3 : d4;
    } else {
        off = (b - 5 * WB) * 1024;
        src = s5; dst = d5;
    }
    const int i = off + threadIdx.x * 4;
    float4 v = *(const float4*)(src + i);
    v.x = to_tf32(v.x); v.y = to_tf32(v.y);
    v.z = to_tf32(v.z); v.w = to_tf32(v.w);
    *(float4*)(dst + i) = v;
}

// ---------------------------------------------------------------------------
// Per-batch transpose with tf32 round: X[z*SEQ+n][h] -> Y[z][h][n]
// ---------------------------------------------------------------------------
__global__ void __launch_bounds__(256) transpose_k(const float* __restrict__ X,
                                                  float* __restrict__ Y)
{
    __shared__ float t[32][33];
    const int z = blockIdx.z, n0 = blockIdx.x * 32, h0 = blockIdx.y * 32;
    const int tx = threadIdx.x & 31, ty = threadIdx.x >> 5;
    #pragma unroll
    for (int i = 0; i < 4; i++) {
        const int rr = ty + 8 * i;
        t[rr][tx] = X[((size_t)z * SEQ + n0 + rr) * HD + h0 + tx];
    }
    __syncthreads();
    #pragma unroll
    for (int i = 0; i < 4; i++) {
        const int rr = ty + 8 * i;
        Y[((size_t)z * HD + h0 + rr) * SEQ + n0 + tx] = to_tf32(t[tx][rr]);
    }
}

// ---------------------------------------------------------------------------
// Combine per-tile partial sums into 1/rowsum
// ---------------------------------------------------------------------------
__global__ void __launch_bounds__(256) rinv_k(const float* __restrict__ P,
                                             float* __restrict__ R)
{
    const int i = blockIdx.x * 256 + threadIdx.x;
    const int z = i >> 10, row = i & 1023;
    float l = 0.f;
    #pragma unroll
    for (int nt = 0; nt < 8; nt++)
        l += P[(((size_t)z * 8 + nt) << 10) + row];
    R[i] = 1.f / l;
}

// ---------------------------------------------------------------------------
// Y = tf32(relu(LN(X))) rowwise over H=256. One warp per row.
// ---------------------------------------------------------------------------
__global__ void __launch_bounds__(256) relu_ln_k(
    const float* __restrict__ X, const float* __restrict__ G,
    const float* __restrict__ Bt, float* __restrict__ Y)
{
    const int row  = blockIdx.x * 8 + (threadIdx.x >> 5);
    const int lane = threadIdx.x & 31;
    const float4* x4 = reinterpret_cast<const float4*>(X + (size_t)row * HD);
    float4 a = x4[lane], b = x4[lane + 32];

    float s = a.x + a.y + a.z + a.w + b.x + b.y + b.z + b.w;
    s = wsum(s);
    const float mu = s * (1.f / HD);
    a.x -= mu; a.y -= mu; a.z -= mu; a.w -= mu;
    b.x -= mu; b.y -= mu; b.z -= mu; b.w -= mu;
    float q = a.x*a.x + a.y*a.y + a.z*a.z + a.w*a.w
            + b.x*b.x + b.y*b.y + b.z*b.z + b.w*b.w;
    q = wsum(q);
    const float inv = rsqrtf(q * (1.f / HD) + 1e-5f);

    const float4* g4 = reinterpret_cast<const float4*>(G);
    const float4* c4 = reinterpret_cast<const float4*>(Bt);
    float4 g0 = g4[lane], g1 = g4[lane + 32];
    float4 c0 = c4[lane], c1 = c4[lane + 32];

    float4 o0, o1;
    o0.x = to_tf32(fmaxf(a.x * inv * g0.x + c0.x, 0.f));
    o0.y = to_tf32(fmaxf(a.y * inv * g0.y + c0.y, 0.f));
    o0.z = to_tf32(fmaxf(a.z * inv * g0.z + c0.z, 0.f));
    o0.w = to_tf32(fmaxf(a.w * inv * g0.w + c0.w, 0.f));
    o1.x = to_tf32(fmaxf(b.x * inv * g1.x + c1.x, 0.f));
    o1.y = to_tf32(fmaxf(b.y * inv * g1.y + c1.y, 0.f));
    o1.z = to_tf32(fmaxf(b.z * inv * g1.z + c1.z, 0.f));
    o1.w = to_tf32(fmaxf(b.w * inv * g1.w + c1.w, 0.f));

    float4* y4 = reinterpret_cast<float4*>(Y + (size_t)row * HD);
    y4[lane] = o0; y4[lane + 32] = o1;
}

// ---------------------------------------------------------------------------
// Y = LN(Xa) + LN(Xb); doRelu -> relu + tf32 round (intermediate layers).
// ---------------------------------------------------------------------------
__global__ void __launch_bounds__(256) dual_ln_add_k(
    const float* __restrict__ Xa, const float* __restrict__ Xb,
    const float* __restrict__ Ga, const float* __restrict__ Ba,
    const float* __restrict__ Gb, const float* __restrict__ Bb,
    float* __restrict__ Y, int doRelu)
{
    const int row  = blockIdx.x * 8 + (threadIdx.x >> 5);
    const int lane = threadIdx.x & 31;

    const float4* xa4 = reinterpret_cast<const float4*>(Xa + (size_t)row * HD);
    const float4* xb4 = reinterpret_cast<const float4*>(Xb + (size_t)row * HD);
    float4 a0 = xa4[lane], a1 = xa4[lane + 32];
    float4 b0 = xb4[lane], b1 = xb4[lane + 32];

    float sa = a0.x+a0.y+a0.z+a0.w + a1.x+a1.y+a1.z+a1.w;
    float sb = b0.x+b0.y+b0.z+b0.w + b1.x+b1.y+b1.z+b1.w;
    sa = wsum(sa); sb = wsum(sb);
    const float mua = sa * (1.f / HD), mub = sb * (1.f / HD);
    a0.x-=mua; a0.y-=mua; a0.z-=mua; a0.w-=mua;
    a1.x-=mua; a1.y-=mua; a1.z-=mua; a1.w-=mua;
    b0.x-=mub; b0.y-=mub; b0.z-=mub; b0.w-=mub;
    b1.x-=mub; b1.y-=mub; b1.z-=mub; b1.w-=mub;
    float qa = a0.x*a0.x+a0.y*a0.y+a0.z*a0.z+a0.w*a0.w
             + a1.x*a1.x+a1.y*a1.y+a1.z*a1.z+a1.w*a1.w;
    float qb = b0.x*b0.x+b0.y*b0.y+b0.z*b0.z+b0.w*b0.w
             + b1.x*b1.x+b1.y*b1.y+b1.z*b1.z+b1.w*b1.w;
    qa = wsum(qa); qb = wsum(qb);
    const float inva = rsqrtf(qa * (1.f / HD) + 1e-5f);
    const float invb = rsqrtf(qb * (1.f / HD) + 1e-5f);

    const float4* ga4 = reinterpret_cast<const float4*>(Ga);
    const float4* ba4 = reinterpret_cast<const float4*>(Ba);
    const float4* gb4 = reinterpret_cast<const float4*>(Gb);
    const float4* bb4 = reinterpret_cast<const float4*>(Bb);
    float4 ga0 = ga4[lane], ga1 = ga4[lane + 32];
    float4 ca0 = ba4[lane], ca1 = ba4[lane + 32];
    float4 gb0 = gb4[lane], gb1 = gb4[lane + 32];
    float4 cb0 = bb4[lane], cb1 = bb4[lane + 32];

    float4 o0, o1;
    o0.x = (a0.x*inva*ga0.x + ca0.x) + (b0.x*invb*gb0.x + cb0.x);
    o0.y = (a0.y*inva*ga0.y + ca0.y) + (b0.y*invb*gb0.y + cb0.y);
    o0.z = (a0.z*inva*ga0.z + ca0.z) + (b0.z*invb*gb0.z + cb0.z);
    o0.w = (a0.w*inva*ga0.w + ca0.w) + (b0.w*invb*gb0.w + cb0.w);
    o1.x = (a1.x*inva*ga1.x + ca1.x) + (b1.x*invb*gb1.x + cb1.x);
    o1.y = (a1.y*inva*ga1.y + ca1.y) + (b1.y*invb*gb1.y + cb1.y);
    o1.z = (a1.z*inva*ga1.z + ca1.z) + (b1.z*invb*gb1.z + cb1.z);
    o1.w = (a1.w*inva*ga1.w + ca1.w) + (b1.w*invb*gb1.w + cb1.w);
    if (doRelu) {
        o0.x = to_tf32(fmaxf(o0.x, 0.f)); o0.y = to_tf32(fmaxf(o0.y, 0.f));
        o0.z = to_tf32(fmaxf(o0.z, 0.f)); o0.w = to_tf32(fmaxf(o0.w, 0.f));
        o1.x = to_tf32(fmaxf(o1.x, 0.f)); o1.y = to_tf32(fmaxf(o1.y, 0.f));
        o1.z = to_tf32(fmaxf(o1.z, 0.f)); o1.w = to_tf32(fmaxf(o1.w, 0.f));
    }

    float4* y4 = reinterpret_cast<float4*>(Y + (size_t)row * HD);
    y4[lane] = o0; y4[lane + 32] = o1;
}

// ---------------------------------------------------------------------------
// Host launch
// ---------------------------------------------------------------------------
extern "C" void kernel_launch(void* const* d_in, const int* in_sizes, int n_in,
                              void* d_out, int out_size)
{
    (void)in_sizes; (void)n_in; (void)out_size;
    const float* feats   = (const float*)d_in[0];
    const float* masks   = (const float*)d_in[1];
    const float* qw      = (const float*)d_in[2];
    const float* qbias   = (const float*)d_in[3];
    const float* kw      = (const float*)d_in[4];
    const float* kbias   = (const float*)d_in[5];
    const float* vw      = (const float*)d_in[6];
    const float* vbias   = (const float*)d_in[7];
    const float* alng    = (const float*)d_in[8];
    const float* alnb    = (const float*)d_in[9];
    const float* caw     = (const float*)d_in[10];
    const float* cabias  = (const float*)d_in[11];
    const float* calng   = (const float*)d_in[12];
    const float* calnb   = (const float*)d_in[13];
    const float* lw      = (const float*)d_in[14];
    const float* lbias   = (const float*)d_in[15];
    const float* llng    = (const float*)d_in[16];
    const float* llnb    = (const float*)d_in[17];
    float* out = (float*)d_out;

    float *Q, *K, *V, *VT, *O, *X1, *T1, *T2, *F, *S, *P, *Ri, *WR;
    cudaGetSymbolAddress((void**)&Q,  g_Q);
    cudaGetSymbolAddress((void**)&K,  g_K);
    cudaGetSymbolAddress((void**)&V,  g_V);
    cudaGetSymbolAddress((void**)&VT, g_VT);
    cudaGetSymbolAddress((void**)&O,  g_O);
    cudaGetSymbolAddress((void**)&X1, g_X1);
    cudaGetSymbolAddress((void**)&T1, g_T1);
    cudaGetSymbolAddress((void**)&T2, g_T2);
    cudaGetSymbolAddress((void**)&F,  g_F);
    cudaGetSymbolAddress((void**)&S,  g_S);
    cudaGetSymbolAddress((void**)&P,  g_P);
    cudaGetSymbolAddress((void**)&Ri, g_Ri);
    cudaGetSymbolAddress((void**)&WR, g_WR);

    cudaFuncSetAttribute(gemm_k<0>, cudaFuncAttributeMaxDynamicSharedMemorySize, GEMM_SMEM);
    cudaFuncSetAttribute(gemm_k<1>, cudaFuncAttributeMaxDynamicSharedMemorySize, GEMM_SMEM);
    cudaFuncSetAttribute(gemm_k<3>, cudaFuncAttributeMaxDynamicSharedMemorySize, GEMM_SMEM);
    cudaFuncSetAttribute(proj4_k,   cudaFuncAttributeMaxDynamicSharedMemorySize, GEMM_SMEM);

    float* qwR = WR + 0 * (size_t)WN;
    float* kwR = WR + 1 * (size_t)WN;
    float* vwR = WR + 2 * (size_t)WN;
    float* cwR = WR + 3 * (size_t)WN;
    float* lwR = WR + 4 * (size_t)WN;

    const dim3 blk(256);
    // launch #1: all rounding in one pass
    round6_k<<<dim3(5 * WB + FB), blk>>>(qw, kw, vw, caw, lw, feats,
                                         qwR, kwR, vwR, cwR, lwR, F);

    const dim3 gProj(HD / BN, MTOT / BM, 1);           // (2, 256) for T1
    const dim3 gProj4(8, MTOT / BM, 1);                // (8, 256) merged QKV+T2
    const dim3 gScore(SEQ / BN, SEQ / BM, BATCH);      // (8, 8, 32)
    const dim3 gPV(HD / BN, SEQ / BM, BATCH);          // (2, 8, 32)
    const dim3 gTr(SEQ / 32, HD / 32, BATCH);

    for (int i = 0; i < 3; i++) {
        const size_t wOff = (size_t)i * HD * HD;
        const size_t bOff = (size_t)i * HD;

        // launches per layer: proj4(2), transpose(3), scores(4), rinv(5),
        // PV(6 <- ncu -s 5 -c 1 capture target), relu_ln(7), T1(8), dual(9)
        proj4_k<<<gProj4, blk, GEMM_SMEM>>>(F,
                                 qwR + wOff, kwR + wOff, vwR + wOff, lwR + wOff,
                                 qbias + bOff, kbias + bOff, vbias + bOff, lbias + bOff,
                                 Q, K, V, T2);

        transpose_k<<<gTr, blk>>>(V, VT);

        gemm_k<1><<<gScore, blk, GEMM_SMEM>>>(Q, K, masks, S,
                                   HD, HD, HD, SEQ,
                                   (size_t)SEQ * HD, (size_t)SEQ * HD,
                                   (size_t)SEQ * SEQ, SEQ, P, 0);

        rinv_k<<<MTOT / 256, blk>>>(P, Ri);

        gemm_k<3><<<gPV, blk, GEMM_SMEM>>>(S, VT, Ri, O,
                                SEQ, SEQ, SEQ, HD,
                                (size_t)SEQ * SEQ, (size_t)HD * SEQ,
                                (size_t)SEQ * HD, SEQ, nullptr, 0);

        relu_ln_k<<<MTOT / 8, blk>>>(O, alng + bOff, alnb + bOff, X1);

        gemm_k<0><<<gProj, blk, GEMM_SMEM>>>(X1, cwR + wOff, cabias + bOff, T1,
                                  HD, HD, HD, HD, 0, 0, 0, 0, nullptr, 0);

        dual_ln_add_k<<<MTOT / 8, blk>>>(T1, T2,
                                         calng + bOff, calnb + bOff,
                                         llng + bOff, llnb + bOff,
                                         (i == 2) ? out : F, (i < 2) ? 1 : 0);
    }
}

// round 13
// speedup vs baseline: 1.0585x; 1.0585x over previous
#include <cuda_runtime.h>
#include <cstdint>

#define DEV_INLINE __device__ __forceinline__

// Problem constants
constexpr int BATCH = 32;
constexpr int SEQ   = 1024;
constexpr int HD    = 256;
constexpr int MTOT  = BATCH * SEQ;   // 32768

// GEMM tiling (all GEMMs are NT: C[M,N] = A[M,K] @ B[N,K]^T, K-major operands)
// 256 threads / 8 warps (4m x 2n), warp tile 32x64 (R10-proven shape).
constexpr int BM = 128, BN = 128, BK = 16;
constexpr int ST = 20;                    // padded smem row stride (floats)
constexpr int TILE_WORDS = BM * ST;       // 2560 floats per operand tile
constexpr int STAGES = 4;                 // 3 tile-loads in flight (R10-proven)
constexpr int STAGE_BYTES = 2 * TILE_WORDS * 4;       // A+B per stage, 20480 B
constexpr int GEMM_SMEM = STAGES * STAGE_BYTES;       // 81920 B dynamic

// ---------------------------------------------------------------------------
// Scratch (device globals: the sanctioned no-alloc path)
// ---------------------------------------------------------------------------
__device__ float g_Q [(size_t)MTOT * HD];
__device__ float g_K [(size_t)MTOT * HD];
__device__ float g_V [(size_t)MTOT * HD];
__device__ float g_VT[(size_t)MTOT * HD];           // per-batch transposed V (tf32)
__device__ float g_O [(size_t)MTOT * HD];
__device__ float g_X1[(size_t)MTOT * HD];
__device__ float g_T1[(size_t)MTOT * HD];
__device__ float g_T2[(size_t)MTOT * HD];
__device__ float g_F [(size_t)MTOT * HD];           // rounded features
__device__ float g_S [(size_t)BATCH * SEQ * SEQ];   // 128 MB: exp(scores), tf32
__device__ float g_P [(size_t)BATCH * 8 * SEQ];     // per n-tile partial row sums
__device__ float g_WR[(size_t)5 * 3 * HD * HD];     // rounded weights (q,k,v,ca,l)

// ---------------------------------------------------------------------------
// Helpers
// ---------------------------------------------------------------------------
DEV_INLINE float to_tf32(float x) {
    unsigned u;
    asm("cvt.rna.tf32.f32 %0, %1;" : "=r"(u) : "f"(x));
    return __uint_as_float(u);
}

DEV_INLINE void mma_tf32(float c[4], const unsigned a[4], const unsigned b[2]) {
    asm volatile(
        "mma.sync.aligned.m16n8k8.row.col.f32.tf32.tf32.f32 "
        "{%0,%1,%2,%3}, {%4,%5,%6,%7}, {%8,%9}, {%0,%1,%2,%3};"
        : "+f"(c[0]), "+f"(c[1]), "+f"(c[2]), "+f"(c[3])
        : "r"(a[0]), "r"(a[1]), "r"(a[2]), "r"(a[3]), "r"(b[0]), "r"(b[1]));
}

DEV_INLINE void ldsm4(uint32_t addr, unsigned& r0, unsigned& r1,
                      unsigned& r2, unsigned& r3) {
    asm volatile("ldmatrix.sync.aligned.m8n8.x4.shared.b16 {%0,%1,%2,%3}, [%4];"
                 : "=r"(r0), "=r"(r1), "=r"(r2), "=r"(r3) : "r"(addr));
}

DEV_INLINE uint32_t smem_u32(const void* p) {
    uint32_t a;
    asm("{ .reg .u64 t; cvta.to.shared.u64 t, %1; cvt.u32.u64 %0, t; }" : "=r"(a) : "l"(p));
    return a;
}

DEV_INLINE void cp16(uint32_t dst, const void* src) {
    asm volatile("cp.async.cg.shared.global [%0], [%1], 16;"
                 :: "r"(dst), "l"(src) : "memory");
}

DEV_INLINE float wsum(float v) {
    #pragma unroll
    for (int o = 16; o; o >>= 1) v += __shfl_xor_sync(0xffffffffu, v, o);
    return v;
}

// ---------------------------------------------------------------------------
// Shared GEMM body: tf32 NT, cp.async 4-stage BK=16 pipeline, ldmatrix frags.
// 256 threads, 8 warps (4m x 2n), warp tile 32x64.
// ALL global operands must already be tf32-rounded.
//   EPI 0: C = A@B^T + bias[col]; roundOut!=0 -> tf32-round stores
//   EPI 1: scores: store tf32(exp(scale*s + shift-inv mask bias)), row partials
//   EPI 3: C = (A@B^T) / rowsum; aux = P partials base (8 tiles x SEQ rows)
// ---------------------------------------------------------------------------
template<int EPI>
DEV_INLINE void gemm_body(
    const float* __restrict__ A, const float* __restrict__ B,
    const float* __restrict__ auxp, float* __restrict__ C,
    int Kdim, int ldA, int ldB, int ldC,
    int m0, int n0, float* __restrict__ PpartDst, int roundOut)
{
    extern __shared__ float smem[];
    const uint32_t sbase = smem_u32(smem);

    const int tid  = threadIdx.x;
    const int warp = tid >> 5, lane = tid & 31;
    const int wm = warp >> 1, wn = warp & 1;
    const int gr = lane >> 2, tig = lane & 3;

    float acc[2][8][4];
    #pragma unroll
    for (int t = 0; t < 2; t++)
        #pragma unroll
        for (int j = 0; j < 8; j++)
            #pragma unroll
            for (int q = 0; q < 4; q++) acc[t][j][q] = 0.f;

    // copy indices: thread -> rows ar, ar+64; k cols ac..ac+3 (16B each)
    const int ar = tid >> 2;
    const int ac = (tid & 3) * 4;
    const float* gA0 = A + (size_t)(m0 + ar) * ldA + ac;
    const float* gA1 = gA0 + (size_t)64 * ldA;
    const float* gB0 = B + (size_t)(n0 + ar) * ldB + ac;
    const float* gB1 = gB0 + (size_t)64 * ldB;
    const uint32_t so = (uint32_t)(ar * ST + ac) * 4;

    // ldmatrix per-lane coordinates (byte offsets, stage-relative)
    const int la_row = lane & 15;
    const int la_k   = (lane >> 4) * 4;
    const int lb_n   = (lane & 7) + ((lane >> 4) << 3);
    const int lb_k   = ((lane >> 3) & 1) * 4;
    const uint32_t aoff0 = (uint32_t)((wm * 32 + la_row) * ST + la_k) * 4;
    const uint32_t aoff1 = aoff0 + 16 * ST * 4;
    uint32_t boff[4];
    #pragma unroll
    for (int jb = 0; jb < 4; jb++)
        boff[jb] = (uint32_t)((wn * 64 + jb * 16 + lb_n) * ST + lb_k) * 4;

    const int KB = Kdim / BK;
    auto issue = [&](int kt) {
        const uint32_t st = sbase + (uint32_t)(kt & (STAGES - 1)) * STAGE_BYTES;
        const int k0 = kt * BK;
        cp16(st + so, gA0 + k0);
        cp16(st + so + 64 * ST * 4, gA1 + k0);
        cp16(st + TILE_WORDS * 4 + so, gB0 + k0);
        cp16(st + TILE_WORDS * 4 + so + 64 * ST * 4, gB1 + k0);
    };

    // prologue: stages 0..2 (KB >= 8 in all uses)
    issue(0);
    asm volatile("cp.async.commit_group;" ::: "memory");
    issue(1);
    asm volatile("cp.async.commit_group;" ::: "memory");
    issue(2);
    asm volatile("cp.async.commit_group;" ::: "memory");

    for (int kt = 0; kt < KB; kt++) {
        asm volatile("cp.async.wait_group %0;" :: "n"(STAGES - 2) : "memory");
        __syncthreads();
        if (kt + STAGES - 1 < KB) issue(kt + STAGES - 1);
        // ALWAYS commit so the pending-group count stays constant (tail-safe)
        asm volatile("cp.async.commit_group;" ::: "memory");

        const uint32_t stA = sbase + (uint32_t)(kt & (STAGES - 1)) * STAGE_BYTES;
        const uint32_t stB = stA + TILE_WORDS * 4;
        #pragma unroll
        for (int kk = 0; kk < 2; kk++) {
            unsigned af[2][4];
            ldsm4(stA + aoff0 + kk * 32, af[0][0], af[0][1], af[0][2], af[0][3]);
            ldsm4(stA + aoff1 + kk * 32, af[1][0], af[1][1], af[1][2], af[1][3]);
            unsigned bf[4][4];
            #pragma unroll
            for (int jb = 0; jb < 4; jb++)
                ldsm4(stB + boff[jb] + kk * 32,
                      bf[jb][0], bf[jb][1], bf[jb][2], bf[jb][3]);
            #pragma unroll
            for (int j = 0; j < 8; j++) {
                const unsigned* bp = &bf[j >> 1][(j & 1) * 2];
                mma_tf32(acc[0][j], af[0], bp);
                mma_tf32(acc[1][j], af[1], bp);
            }
        }
    }

    // Epilogue
    const float SCALE = 0.0625f;  // 1/sqrt(256)
    float rs[2][2];
    rs[0][0] = rs[0][1] = rs[1][0] = rs[1][1] = 0.f;

    #pragma unroll
    for (int t = 0; t < 2; t++) {
        const int r0 = m0 + wm * 32 + t * 16 + gr;
        const int r1 = r0 + 8;
        float mq0 = 0.f, mq1 = 0.f, rv0 = 0.f, rv1 = 0.f;
        if (EPI == 1) { mq0 = auxp[r0]; mq1 = auxp[r1]; }
        if (EPI == 3) {
            // inline 1/rowsum from the 8 per-n-tile partials (same add order
            // as the old rinv_k: nt ascending)
            float l0 = 0.f, l1 = 0.f;
            #pragma unroll
            for (int nt = 0; nt < 8; nt++) {
                l0 += auxp[(nt << 10) + r0];
                l1 += auxp[(nt << 10) + r1];
            }
            rv0 = 1.f / l0;
            rv1 = 1.f / l1;
        }
        #pragma unroll
        for (int j = 0; j < 8; j++) {
            const int c = n0 + wn * 64 + j * 8 + 2 * tig;
            float x0 = acc[t][j][0], x1 = acc[t][j][1];
            float x2 = acc[t][j][2], x3 = acc[t][j][3];
            if (EPI == 0) {
                const float b0 = auxp[c], b1 = auxp[c + 1];
                float y0 = x0 + b0, y1 = x1 + b1;
                float y2 = x2 + b0, y3 = x3 + b1;
                if (roundOut) {
                    y0 = to_tf32(y0); y1 = to_tf32(y1);
                    y2 = to_tf32(y2); y3 = to_tf32(y3);
                }
                float2 v0 = {y0, y1};
                float2 v1 = {y2, y3};
                *(float2*)&C[(size_t)r0 * ldC + c] = v0;
                *(float2*)&C[(size_t)r1 * ldC + c] = v1;
            } else if (EPI == 1) {
                // shift-invariant mask bias: mq ? (mk ? +1 : masked->0) : 0
                const float mc0 = auxp[c], mc1 = auxp[c + 1];
                float e00, e01, e10, e11;
                if (mq0 > 0.5f) {
                    e00 = (mc0 > 0.5f) ? __expf(x0 * SCALE + 1.f) : 0.f;
                    e01 = (mc1 > 0.5f) ? __expf(x1 * SCALE + 1.f) : 0.f;
                } else {
                    e00 = __expf(x0 * SCALE);
                    e01 = __expf(x1 * SCALE);
                }
                if (mq1 > 0.5f) {
                    e10 = (mc0 > 0.5f) ? __expf(x2 * SCALE + 1.f) : 0.f;
                    e11 = (mc1 > 0.5f) ? __expf(x3 * SCALE + 1.f) : 0.f;
                } else {
                    e10 = __expf(x2 * SCALE);
                    e11 = __expf(x3 * SCALE);
                }
                // round first so PV operand and row sum are consistent
                e00 = to_tf32(e00); e01 = to_tf32(e01);
                e10 = to_tf32(e10); e11 = to_tf32(e11);
                rs[t][0] += e00 + e01;
                rs[t][1] += e10 + e11;
                float2 v0 = {e00, e01};
                float2 v1 = {e10, e11};
                *(float2*)&C[(size_t)r0 * ldC + c] = v0;
                *(float2*)&C[(size_t)r1 * ldC + c] = v1;
            } else {
                float2 v0 = {x0 * rv0, x1 * rv0};
                float2 v1 = {x2 * rv1, x3 * rv1};
                *(float2*)&C[(size_t)r0 * ldC + c] = v0;
                *(float2*)&C[(size_t)r1 * ldC + c] = v1;
            }
        }
    }

    if (EPI == 1) {
        asm volatile("cp.async.wait_group 0;" ::: "memory");
        __syncthreads();   // all smem use done before reuse as reduce buffer
        float* part = smem;
        #pragma unroll
        for (int t = 0; t < 2; t++) {
            #pragma unroll
            for (int rr = 0; rr < 2; rr++) {
                float v = rs[t][rr];
                v += __shfl_xor_sync(0xffffffffu, v, 1);
                v += __shfl_xor_sync(0xffffffffu, v, 2);
                if (tig == 0)
                    part[wn * 128 + wm * 32 + t * 16 + rr * 8 + gr] = v;
            }
        }
        __syncthreads();
        if (tid < 128)
            PpartDst[tid] = part[tid] + part[128 + tid];
    }
}

// ---------------------------------------------------------------------------
// Generic batched GEMM wrapper
//   EPI 1: Ppart = output partials;  EPI 3: aux = P partials (auxStride 8*SEQ)
// ---------------------------------------------------------------------------
template<int EPI>
__global__ void __launch_bounds__(256, 2) gemm_k(
    const float* __restrict__ Ag, const float* __restrict__ Bg,
    const float* __restrict__ aux, float* __restrict__ Cg,
    int Kdim, int ldA, int ldB, int ldC,
    size_t sA, size_t sB, size_t sC, int auxStride,
    float* __restrict__ Ppart, int roundOut)
{
    const int z = blockIdx.z;
    const int m0 = blockIdx.y * BM;
    const int n0 = blockIdx.x * BN;
    float* pdst = (EPI == 1)
        ? Ppart + ((size_t)z * 8 + blockIdx.x) * SEQ + m0 : nullptr;
    gemm_body<EPI>(Ag + (size_t)z * sA, Bg + (size_t)z * sB,
                   aux + (size_t)z * auxStride, Cg + (size_t)z * sC,
                   Kdim, ldA, ldB, ldC, m0, n0, pdst, roundOut);
}

// ---------------------------------------------------------------------------
// 4-way merged projection: Q/K/V/T2 = A @ {qw,kw,vw,lw}^T + bias
// grid (8, 256): blockIdx.x>>1 selects matrix, &1 selects n-half.
// Q,K outputs tf32-rounded (GEMM operands); V,T2 left fp32.
// ---------------------------------------------------------------------------
__global__ void __launch_bounds__(256, 2) proj4_k(
    const float* __restrict__ A,
    const float* __restrict__ w0, const float* __restrict__ w1,
    const float* __restrict__ w2, const float* __restrict__ w3,
    const float* __restrict__ b0, const float* __restrict__ b1,
    const float* __restrict__ b2, const float* __restrict__ b3,
    float* __restrict__ c0, float* __restrict__ c1,
    float* __restrict__ c2, float* __restrict__ c3)
{
    const int g  = blockIdx.x >> 1;
    const int n0 = (blockIdx.x & 1) * BN;
    const int m0 = blockIdx.y * BM;
    const float* W    = (g == 0) ? w0 : (g == 1) ? w1 : (g == 2) ? w2 : w3;
    const float* bias = (g == 0) ? b0 : (g == 1) ? b1 : (g == 2) ? b2 : b3;
    float*       C    = (g == 0) ? c0 : (g == 1) ? c1 : (g == 2) ? c2 : c3;
    gemm_body<0>(A, W, bias, C, HD, HD, HD, HD, m0, n0, nullptr, (g < 2) ? 1 : 0);
}

// ---------------------------------------------------------------------------
// Single-launch tf32 rounding of 5 weight tensors + feats.
// Blocks [0, 5*WB): weights (WB blocks each); [5*WB, 5*WB+FB): feats.
// ---------------------------------------------------------------------------
constexpr int WN = 3 * HD * HD;          // 196608 floats per weight tensor
constexpr int WB = WN / 1024;            // 192 blocks per weight tensor
constexpr int FB = MTOT * HD / 1024;     // 8192 blocks for feats

__global__ void __launch_bounds__(256) round6_k(
    const float* __restrict__ s0, const float* __restrict__ s1,
    const float* __restrict__ s2, const float* __restrict__ s3,
    const float* __restrict__ s4, const float* __restrict__ s5,
    float* __restrict__ d0, float* __restrict__ d1,
    float* __restrict__ d2, float* __restrict__ d3,
    float* __restrict__ d4, float* __restrict__ d5)
{
    const int b = blockIdx.x;
    const float* src; float* dst; int off;
    if (b < 5 * WB) {
        const int seg = b / WB;
        off = (b - seg * WB) * 1024;
        src = (seg == 0) ? s0 : (seg == 1) ? s1 : (seg == 2) ? s2
            : (seg == 3) ? s3 : s4;
        dst = (seg == 0) ? d0 : (seg == 1) ? d1 : (seg == 2) ? d2
            : (seg == 3) ? d3 : d4;
    } else {
        off = (b - 5 * WB) * 1024;
        src = s5; dst = d5;
    }
    const int i = off + threadIdx.x * 4;
    float4 v = *(const float4*)(src + i);
    v.x = to_tf32(v.x); v.y = to_tf32(v.y);
    v.z = to_tf32(v.z); v.w = to_tf32(v.w);
    *(float4*)(dst + i) = v;
}

// ---------------------------------------------------------------------------
// Per-batch transpose with tf32 round: X[z*SEQ+n][h] -> Y[z][h][n]
// ---------------------------------------------------------------------------
__global__ void __launch_bounds__(256) transpose_k(const float* __restrict__ X,
                                                  float* __restrict__ Y)
{
    __shared__ float t[32][33];
    const int z = blockIdx.z, n0 = blockIdx.x * 32, h0 = blockIdx.y * 32;
    const int tx = threadIdx.x & 31, ty = threadIdx.x >> 5;
    #pragma unroll
    for (int i = 0; i < 4; i++) {
        const int rr = ty + 8 * i;
        t[rr][tx] = X[((size_t)z * SEQ + n0 + rr) * HD + h0 + tx];
    }
    __syncthreads();
    #pragma unroll
    for (int i = 0; i < 4; i++) {
        const int rr = ty + 8 * i;
        Y[((size_t)z * HD + h0 + rr) * SEQ + n0 + tx] = to_tf32(t[tx][rr]);
    }
}

// ---------------------------------------------------------------------------
// Y = tf32(relu(LN(X))) rowwise over H=256. One warp per row.
// ---------------------------------------------------------------------------
__global__ void __launch_bounds__(256) relu_ln_k(
    const float* __restrict__ X, const float* __restrict__ G,
    const float* __restrict__ Bt, float* __restrict__ Y)
{
    const int row  = blockIdx.x * 8 + (threadIdx.x >> 5);
    const int lane = threadIdx.x & 31;
    const float4* x4 = reinterpret_cast<const float4*>(X + (size_t)row * HD);
    float4 a = x4[lane], b = x4[lane + 32];

    float s = a.x + a.y + a.z + a.w + b.x + b.y + b.z + b.w;
    s = wsum(s);
    const float mu = s * (1.f / HD);
    a.x -= mu; a.y -= mu; a.z -= mu; a.w -= mu;
    b.x -= mu; b.y -= mu; b.z -= mu; b.w -= mu;
    float q = a.x*a.x + a.y*a.y + a.z*a.z + a.w*a.w
            + b.x*b.x + b.y*b.y + b.z*b.z + b.w*b.w;
    q = wsum(q);
    const float inv = rsqrtf(q * (1.f / HD) + 1e-5f);

    const float4* g4 = reinterpret_cast<const float4*>(G);
    const float4* c4 = reinterpret_cast<const float4*>(Bt);
    float4 g0 = g4[lane], g1 = g4[lane + 32];
    float4 c0 = c4[lane], c1 = c4[lane + 32];

    float4 o0, o1;
    o0.x = to_tf32(fmaxf(a.x * inv * g0.x + c0.x, 0.f));
    o0.y = to_tf32(fmaxf(a.y * inv * g0.y + c0.y, 0.f));
    o0.z = to_tf32(fmaxf(a.z * inv * g0.z + c0.z, 0.f));
    o0.w = to_tf32(fmaxf(a.w * inv * g0.w + c0.w, 0.f));
    o1.x = to_tf32(fmaxf(b.x * inv * g1.x + c1.x, 0.f));
    o1.y = to_tf32(fmaxf(b.y * inv * g1.y + c1.y, 0.f));
    o1.z = to_tf32(fmaxf(b.z * inv * g1.z + c1.z, 0.f));
    o1.w = to_tf32(fmaxf(b.w * inv * g1.w + c1.w, 0.f));

    float4* y4 = reinterpret_cast<float4*>(Y + (size_t)row * HD);
    y4[lane] = o0; y4[lane + 32] = o1;
}

// ---------------------------------------------------------------------------
// Y = LN(Xa) + LN(Xb); doRelu -> relu + tf32 round (intermediate layers).
// ---------------------------------------------------------------------------
__global__ void __launch_bounds__(256) dual_ln_add_k(
    const float* __restrict__ Xa, const float* __restrict__ Xb,
    const float* __restrict__ Ga, const float* __restrict__ Ba,
    const float* __restrict__ Gb, const float* __restrict__ Bb,
    float* __restrict__ Y, int doRelu)
{
    const int row  = blockIdx.x * 8 + (threadIdx.x >> 5);
    const int lane = threadIdx.x & 31;

    const float4* xa4 = reinterpret_cast<const float4*>(Xa + (size_t)row * HD);
    const float4* xb4 = reinterpret_cast<const float4*>(Xb + (size_t)row * HD);
    float4 a0 = xa4[lane], a1 = xa4[lane + 32];
    float4 b0 = xb4[lane], b1 = xb4[lane + 32];

    float sa = a0.x+a0.y+a0.z+a0.w + a1.x+a1.y+a1.z+a1.w;
    float sb = b0.x+b0.y+b0.z+b0.w + b1.x+b1.y+b1.z+b1.w;
    sa = wsum(sa); sb = wsum(sb);
    const float mua = sa * (1.f / HD), mub = sb * (1.f / HD);
    a0.x-=mua; a0.y-=mua; a0.z-=mua; a0.w-=mua;
    a1.x-=mua; a1.y-=mua; a1.z-=mua; a1.w-=mua;
    b0.x-=mub; b0.y-=mub; b0.z-=mub; b0.w-=mub;
    b1.x-=mub; b1.y-=mub; b1.z-=mub; b1.w-=mub;
    float qa = a0.x*a0.x+a0.y*a0.y+a0.z*a0.z+a0.w*a0.w
             + a1.x*a1.x+a1.y*a1.y+a1.z*a1.z+a1.w*a1.w;
    float qb = b0.x*b0.x+b0.y*b0.y+b0.z*b0.z+b0.w*b0.w
             + b1.x*b1.x+b1.y*b1.y+b1.z*b1.z+b1.w*b1.w;
    qa = wsum(qa); qb = wsum(qb);
    const float inva = rsqrtf(qa * (1.f / HD) + 1e-5f);
    const float invb = rsqrtf(qb * (1.f / HD) + 1e-5f);

    const float4* ga4 = reinterpret_cast<const float4*>(Ga);
    const float4* ba4 = reinterpret_cast<const float4*>(Ba);
    const float4* gb4 = reinterpret_cast<const float4*>(Gb);
    const float4* bb4 = reinterpret_cast<const float4*>(Bb);
    float4 ga0 = ga4[lane], ga1 = ga4[lane + 32];
    float4 ca0 = ba4[lane], ca1 = ba4[lane + 32];
    float4 gb0 = gb4[lane], gb1 = gb4[lane + 32];
    float4 cb0 = bb4[lane], cb1 = bb4[lane + 32];

    float4 o0, o1;
    o0.x = (a0.x*inva*ga0.x + ca0.x) + (b0.x*invb*gb0.x + cb0.x);
    o0.y = (a0.y*inva*ga0.y + ca0.y) + (b0.y*invb*gb0.y + cb0.y);
    o0.z = (a0.z*inva*ga0.z + ca0.z) + (b0.z*invb*gb0.z + cb0.z);
    o0.w = (a0.w*inva*ga0.w + ca0.w) + (b0.w*invb*gb0.w + cb0.w);
    o1.x = (a1.x*inva*ga1.x + ca1.x) + (b1.x*invb*gb1.x + cb1.x);
    o1.y = (a1.y*inva*ga1.y + ca1.y) + (b1.y*invb*gb1.y + cb1.y);
    o1.z = (a1.z*inva*ga1.z + ca1.z) + (b1.z*invb*gb1.z + cb1.z);
    o1.w = (a1.w*inva*ga1.w + ca1.w) + (b1.w*invb*gb1.w + cb1.w);
    if (doRelu) {
        o0.x = to_tf32(fmaxf(o0.x, 0.f)); o0.y = to_tf32(fmaxf(o0.y, 0.f));
        o0.z = to_tf32(fmaxf(o0.z, 0.f)); o0.w = to_tf32(fmaxf(o0.w, 0.f));
        o1.x = to_tf32(fmaxf(o1.x, 0.f)); o1.y = to_tf32(fmaxf(o1.y, 0.f));
        o1.z = to_tf32(fmaxf(o1.z, 0.f)); o1.w = to_tf32(fmaxf(o1.w, 0.f));
    }

    float4* y4 = reinterpret_cast<float4*>(Y + (size_t)row * HD);
    y4[lane] = o0; y4[lane + 32] = o1;
}

// ---------------------------------------------------------------------------
// Host launch
// ---------------------------------------------------------------------------
extern "C" void kernel_launch(void* const* d_in, const int* in_sizes, int n_in,
                              void* d_out, int out_size)
{
    (void)in_sizes; (void)n_in; (void)out_size;
    const float* feats   = (const float*)d_in[0];
    const float* masks   = (const float*)d_in[1];
    const float* qw      = (const float*)d_in[2];
    const float* qbias   = (const float*)d_in[3];
    const float* kw      = (const float*)d_in[4];
    const float* kbias   = (const float*)d_in[5];
    const float* vw      = (const float*)d_in[6];
    const float* vbias   = (const float*)d_in[7];
    const float* alng    = (const float*)d_in[8];
    const float* alnb    = (const float*)d_in[9];
    const float* caw     = (const float*)d_in[10];
    const float* cabias  = (const float*)d_in[11];
    const float* calng   = (const float*)d_in[12];
    const float* calnb   = (const float*)d_in[13];
    const float* lw      = (const float*)d_in[14];
    const float* lbias   = (const float*)d_in[15];
    const float* llng    = (const float*)d_in[16];
    const float* llnb    = (const float*)d_in[17];
    float* out = (float*)d_out;

    float *Q, *K, *V, *VT, *O, *X1, *T1, *T2, *F, *S, *P, *WR;
    cudaGetSymbolAddress((void**)&Q,  g_Q);
    cudaGetSymbolAddress((void**)&K,  g_K);
    cudaGetSymbolAddress((void**)&V,  g_V);
    cudaGetSymbolAddress((void**)&VT, g_VT);
    cudaGetSymbolAddress((void**)&O,  g_O);
    cudaGetSymbolAddress((void**)&X1, g_X1);
    cudaGetSymbolAddress((void**)&T1, g_T1);
    cudaGetSymbolAddress((void**)&T2, g_T2);
    cudaGetSymbolAddress((void**)&F,  g_F);
    cudaGetSymbolAddress((void**)&S,  g_S);
    cudaGetSymbolAddress((void**)&P,  g_P);
    cudaGetSymbolAddress((void**)&WR, g_WR);

    cudaFuncSetAttribute(gemm_k<0>, cudaFuncAttributeMaxDynamicSharedMemorySize, GEMM_SMEM);
    cudaFuncSetAttribute(gemm_k<1>, cudaFuncAttributeMaxDynamicSharedMemorySize, GEMM_SMEM);
    cudaFuncSetAttribute(gemm_k<3>, cudaFuncAttributeMaxDynamicSharedMemorySize, GEMM_SMEM);
    cudaFuncSetAttribute(proj4_k,   cudaFuncAttributeMaxDynamicSharedMemorySize, GEMM_SMEM);

    float* qwR = WR + 0 * (size_t)WN;
    float* kwR = WR + 1 * (size_t)WN;
    float* vwR = WR + 2 * (size_t)WN;
    float* cwR = WR + 3 * (size_t)WN;
    float* lwR = WR + 4 * (size_t)WN;

    const dim3 blk(256);
    // launch #1: all rounding in one pass
    round6_k<<<dim3(5 * WB + FB), blk>>>(qw, kw, vw, caw, lw, feats,
                                         qwR, kwR, vwR, cwR, lwR, F);

    const dim3 gProj(HD / BN, MTOT / BM, 1);           // (2, 256) for T1
    const dim3 gProj4(8, MTOT / BM, 1);                // (8, 256) merged QKV+T2
    const dim3 gScore(SEQ / BN, SEQ / BM, BATCH);      // (8, 8, 32)
    const dim3 gPV(HD / BN, SEQ / BM, BATCH);          // (2, 8, 32)
    const dim3 gTr(SEQ / 32, HD / 32, BATCH);

    for (int i = 0; i < 3; i++) {
        const size_t wOff = (size_t)i * HD * HD;
        const size_t bOff = (size_t)i * HD;

        // launches per layer: proj4(2), transpose(3), scores(4),
        // PV(5), relu_ln(6), T1(7), dual(8)
        proj4_k<<<gProj4, blk, GEMM_SMEM>>>(F,
                                 qwR + wOff, kwR + wOff, vwR + wOff, lwR + wOff,
                                 qbias + bOff, kbias + bOff, vbias + bOff, lbias + bOff,
                                 Q, K, V, T2);

        transpose_k<<<gTr, blk>>>(V, VT);

        gemm_k<1><<<gScore, blk, GEMM_SMEM>>>(Q, K, masks, S,
                                   HD, HD, HD, SEQ,
                                   (size_t)SEQ * HD, (size_t)SEQ * HD,
                                   (size_t)SEQ * SEQ, SEQ, P, 0);

        // PV: rowsum folded into epilogue (aux = P partials, stride 8*SEQ)
        gemm_k<3><<<gPV, blk, GEMM_SMEM>>>(S, VT, P, O,
                                SEQ, SEQ, SEQ, HD,
                                (size_t)SEQ * SEQ, (size_t)HD * SEQ,
                                (size_t)SEQ * HD, 8 * SEQ, nullptr, 0);

        relu_ln_k<<<MTOT / 8, blk>>>(O, alng + bOff, alnb + bOff, X1);

        gemm_k<0><<<gProj, blk, GEMM_SMEM>>>(X1, cwR + wOff, cabias + bOff, T1,
                                  HD, HD, HD, HD, 0, 0, 0, 0, nullptr, 0);

        dual_ln_add_k<<<MTOT / 8, blk>>>(T1, T2,
                                         calng + bOff, calnb + bOff,
                                         llng + bOff, llnb + bOff,
                                         (i == 2) ? out : F, (i < 2) ? 1 : 0);
    }
}

// round 14
// speedup vs baseline: 1.1741x; 1.1093x over previous
#include <cuda_runtime.h>
#include <cuda_bf16.h>
#include <cstdint>

#define DEV_INLINE __device__ __forceinline__

// Problem constants
constexpr int BATCH = 32;
constexpr int SEQ   = 1024;
constexpr int HD    = 256;
constexpr int MTOT  = BATCH * SEQ;   // 32768

// tf32 GEMM tiling (NT: C[M,N] = A[M,K] @ B[N,K]^T, K-major operands)
// 256 threads / 8 warps (4m x 2n), warp tile 32x64 (R10-proven shape).
constexpr int BM = 128, BN = 128, BK = 16;
constexpr int ST = 20;                    // padded smem row stride (floats)
constexpr int TILE_WORDS = BM * ST;       // 2560 floats per operand tile
constexpr int STAGES = 4;                 // 3 tile-loads in flight
constexpr int STAGE_BYTES = 2 * TILE_WORDS * 4;       // A+B per stage, 20480 B
constexpr int GEMM_SMEM = STAGES * STAGE_BYTES;       // 81920 B dynamic

// bf16 PV GEMM tiling: BK2=32 bf16, smem row stride 40 bf16 (80 B, 5 phases)
constexpr int BK2 = 32;
constexpr int ST2 = 40;
constexpr int TILE2_BYTES = 128 * ST2 * 2;            // 10240 B per operand
constexpr int STAGE2_BYTES = 2 * TILE2_BYTES;         // 20480 B
constexpr int PV_SMEM = STAGES * STAGE2_BYTES;        // 81920 B dynamic

// ---------------------------------------------------------------------------
// Scratch (device globals: the sanctioned no-alloc path)
// ---------------------------------------------------------------------------
__device__ float g_Q [(size_t)MTOT * HD];
__device__ float g_K [(size_t)MTOT * HD];
__device__ float g_V [(size_t)MTOT * HD];
__device__ __nv_bfloat16 g_VTh[(size_t)MTOT * HD];     // per-batch V^T, bf16
__device__ float g_O [(size_t)MTOT * HD];
__device__ float g_X1[(size_t)MTOT * HD];
__device__ float g_T1[(size_t)MTOT * HD];
__device__ float g_T2[(size_t)MTOT * HD];
__device__ float g_F [(size_t)MTOT * HD];              // rounded features
__device__ __nv_bfloat16 g_Sh[(size_t)BATCH * SEQ * SEQ];  // 64 MB exp(scores)
__device__ float g_P [(size_t)BATCH * 8 * SEQ];        // per n-tile partial sums
__device__ float g_WR[(size_t)5 * 3 * HD * HD];        // rounded weights

// ---------------------------------------------------------------------------
// Helpers
// ---------------------------------------------------------------------------
DEV_INLINE float to_tf32(float x) {
    unsigned u;
    asm("cvt.rna.tf32.f32 %0, %1;" : "=r"(u) : "f"(x));
    return __uint_as_float(u);
}

DEV_INLINE void mma_tf32(float c[4], const unsigned a[4], const unsigned b[2]) {
    asm volatile(
        "mma.sync.aligned.m16n8k8.row.col.f32.tf32.tf32.f32 "
        "{%0,%1,%2,%3}, {%4,%5,%6,%7}, {%8,%9}, {%0,%1,%2,%3};"
        : "+f"(c[0]), "+f"(c[1]), "+f"(c[2]), "+f"(c[3])
        : "r"(a[0]), "r"(a[1]), "r"(a[2]), "r"(a[3]), "r"(b[0]), "r"(b[1]));
}

DEV_INLINE void mma_bf16(float c[4], const unsigned a[4], const unsigned b[2]) {
    asm volatile(
        "mma.sync.aligned.m16n8k16.row.col.f32.bf16.bf16.f32 "
        "{%0,%1,%2,%3}, {%4,%5,%6,%7}, {%8,%9}, {%0,%1,%2,%3};"
        : "+f"(c[0]), "+f"(c[1]), "+f"(c[2]), "+f"(c[3])
        : "r"(a[0]), "r"(a[1]), "r"(a[2]), "r"(a[3]), "r"(b[0]), "r"(b[1]));
}

DEV_INLINE void ldsm4(uint32_t addr, unsigned& r0, unsigned& r1,
                      unsigned& r2, unsigned& r3) {
    asm volatile("ldmatrix.sync.aligned.m8n8.x4.shared.b16 {%0,%1,%2,%3}, [%4];"
                 : "=r"(r0), "=r"(r1), "=r"(r2), "=r"(r3) : "r"(addr));
}

DEV_INLINE uint32_t smem_u32(const void* p) {
    uint32_t a;
    asm("{ .reg .u64 t; cvta.to.shared.u64 t, %1; cvt.u32.u64 %0, t; }" : "=r"(a) : "l"(p));
    return a;
}

DEV_INLINE void cp16(uint32_t dst, const void* src) {
    asm volatile("cp.async.cg.shared.global [%0], [%1], 16;"
                 :: "r"(dst), "l"(src) : "memory");
}

DEV_INLINE float wsum(float v) {
    #pragma unroll
    for (int o = 16; o; o >>= 1) v += __shfl_xor_sync(0xffffffffu, v, o);
    return v;
}

// ---------------------------------------------------------------------------
// tf32 GEMM body (fp32 K-major operands, pre-rounded to tf32).
//   EPI 0: C = A@B^T + bias[col]; roundOut -> tf32-round stores
//   EPI 1: scores: store bf16(exp(scale*s + shift-inv mask bias)) to C
//          (reinterpreted as bf16*), emit per-row partial sums of the
//          bf16-rounded values
// ---------------------------------------------------------------------------
template<int EPI>
DEV_INLINE void gemm_body(
    const float* __restrict__ A, const float* __restrict__ B,
    const float* __restrict__ auxp, float* __restrict__ C,
    int Kdim, int ldA, int ldB, int ldC,
    int m0, int n0, float* __restrict__ PpartDst, int roundOut)
{
    extern __shared__ float smem[];
    const uint32_t sbase = smem_u32(smem);

    const int tid  = threadIdx.x;
    const int warp = tid >> 5, lane = tid & 31;
    const int wm = warp >> 1, wn = warp & 1;
    const int gr = lane >> 2, tig = lane & 3;

    float acc[2][8][4];
    #pragma unroll
    for (int t = 0; t < 2; t++)
        #pragma unroll
        for (int j = 0; j < 8; j++)
            #pragma unroll
            for (int q = 0; q < 4; q++) acc[t][j][q] = 0.f;

    const int ar = tid >> 2;
    const int ac = (tid & 3) * 4;
    const float* gA0 = A + (size_t)(m0 + ar) * ldA + ac;
    const float* gA1 = gA0 + (size_t)64 * ldA;
    const float* gB0 = B + (size_t)(n0 + ar) * ldB + ac;
    const float* gB1 = gB0 + (size_t)64 * ldB;
    const uint32_t so = (uint32_t)(ar * ST + ac) * 4;

    const int la_row = lane & 15;
    const int la_k   = (lane >> 4) * 4;
    const int lb_n   = (lane & 7) + ((lane >> 4) << 3);
    const int lb_k   = ((lane >> 3) & 1) * 4;
    const uint32_t aoff0 = (uint32_t)((wm * 32 + la_row) * ST + la_k) * 4;
    const uint32_t aoff1 = aoff0 + 16 * ST * 4;
    uint32_t boff[4];
    #pragma unroll
    for (int jb = 0; jb < 4; jb++)
        boff[jb] = (uint32_t)((wn * 64 + jb * 16 + lb_n) * ST + lb_k) * 4;

    const int KB = Kdim / BK;
    auto issue = [&](int kt) {
        const uint32_t st = sbase + (uint32_t)(kt & (STAGES - 1)) * STAGE_BYTES;
        const int k0 = kt * BK;
        cp16(st + so, gA0 + k0);
        cp16(st + so + 64 * ST * 4, gA1 + k0);
        cp16(st + TILE_WORDS * 4 + so, gB0 + k0);
        cp16(st + TILE_WORDS * 4 + so + 64 * ST * 4, gB1 + k0);
    };

    issue(0);
    asm volatile("cp.async.commit_group;" ::: "memory");
    issue(1);
    asm volatile("cp.async.commit_group;" ::: "memory");
    issue(2);
    asm volatile("cp.async.commit_group;" ::: "memory");

    for (int kt = 0; kt < KB; kt++) {
        asm volatile("cp.async.wait_group %0;" :: "n"(STAGES - 2) : "memory");
        __syncthreads();
        if (kt + STAGES - 1 < KB) issue(kt + STAGES - 1);
        asm volatile("cp.async.commit_group;" ::: "memory");

        const uint32_t stA = sbase + (uint32_t)(kt & (STAGES - 1)) * STAGE_BYTES;
        const uint32_t stB = stA + TILE_WORDS * 4;
        #pragma unroll
        for (int kk = 0; kk < 2; kk++) {
            unsigned af[2][4];
            ldsm4(stA + aoff0 + kk * 32, af[0][0], af[0][1], af[0][2], af[0][3]);
            ldsm4(stA + aoff1 + kk * 32, af[1][0], af[1][1], af[1][2], af[1][3]);
            unsigned bf[4][4];
            #pragma unroll
            for (int jb = 0; jb < 4; jb++)
                ldsm4(stB + boff[jb] + kk * 32,
                      bf[jb][0], bf[jb][1], bf[jb][2], bf[jb][3]);
            #pragma unroll
            for (int j = 0; j < 8; j++) {
                const unsigned* bp = &bf[j >> 1][(j & 1) * 2];
                mma_tf32(acc[0][j], af[0], bp);
                mma_tf32(acc[1][j], af[1], bp);
            }
        }
    }

    // Epilogue
    const float SCALE = 0.0625f;  // 1/sqrt(256)
    float rs[2][2];
    rs[0][0] = rs[0][1] = rs[1][0] = rs[1][1] = 0.f;
    __nv_bfloat16* Cb = reinterpret_cast<__nv_bfloat16*>(C);

    #pragma unroll
    for (int t = 0; t < 2; t++) {
        const int r0 = m0 + wm * 32 + t * 16 + gr;
        const int r1 = r0 + 8;
        float mq0 = 0.f, mq1 = 0.f;
        if (EPI == 1) { mq0 = auxp[r0]; mq1 = auxp[r1]; }
        #pragma unroll
        for (int j = 0; j < 8; j++) {
            const int c = n0 + wn * 64 + j * 8 + 2 * tig;
            float x0 = acc[t][j][0], x1 = acc[t][j][1];
            float x2 = acc[t][j][2], x3 = acc[t][j][3];
            if (EPI == 0) {
                const float b0 = auxp[c], b1 = auxp[c + 1];
                float y0 = x0 + b0, y1 = x1 + b1;
                float y2 = x2 + b0, y3 = x3 + b1;
                if (roundOut) {
                    y0 = to_tf32(y0); y1 = to_tf32(y1);
                    y2 = to_tf32(y2); y3 = to_tf32(y3);
                }
                float2 v0 = {y0, y1};
                float2 v1 = {y2, y3};
                *(float2*)&C[(size_t)r0 * ldC + c] = v0;
                *(float2*)&C[(size_t)r1 * ldC + c] = v1;
            } else {
                // shift-invariant mask bias: mq ? (mk ? +1 : masked->0) : 0
                const float mc0 = auxp[c], mc1 = auxp[c + 1];
                float e00, e01, e10, e11;
                if (mq0 > 0.5f) {
                    e00 = (mc0 > 0.5f) ? __expf(x0 * SCALE + 1.f) : 0.f;
                    e01 = (mc1 > 0.5f) ? __expf(x1 * SCALE + 1.f) : 0.f;
                } else {
                    e00 = __expf(x0 * SCALE);
                    e01 = __expf(x1 * SCALE);
                }
                if (mq1 > 0.5f) {
                    e10 = (mc0 > 0.5f) ? __expf(x2 * SCALE + 1.f) : 0.f;
                    e11 = (mc1 > 0.5f) ? __expf(x3 * SCALE + 1.f) : 0.f;
                } else {
                    e10 = __expf(x2 * SCALE);
                    e11 = __expf(x3 * SCALE);
                }
                // bf16-round first so PV operand and rowsum are consistent
                __nv_bfloat16 h00 = __float2bfloat16(e00);
                __nv_bfloat16 h01 = __float2bfloat16(e01);
                __nv_bfloat16 h10 = __float2bfloat16(e10);
                __nv_bfloat16 h11 = __float2bfloat16(e11);
                rs[t][0] += __bfloat162float(h00) + __bfloat162float(h01);
                rs[t][1] += __bfloat162float(h10) + __bfloat162float(h11);
                __nv_bfloat162 p0; p0.x = h00; p0.y = h01;
                __nv_bfloat162 p1; p1.x = h10; p1.y = h11;
                *(__nv_bfloat162*)&Cb[(size_t)r0 * ldC + c] = p0;
                *(__nv_bfloat162*)&Cb[(size_t)r1 * ldC + c] = p1;
            }
        }
    }

    if (EPI == 1) {
        asm volatile("cp.async.wait_group 0;" ::: "memory");
        __syncthreads();   // all smem use done before reuse as reduce buffer
        float* part = smem;
        #pragma unroll
        for (int t = 0; t < 2; t++) {
            #pragma unroll
            for (int rr = 0; rr < 2; rr++) {
                float v = rs[t][rr];
                v += __shfl_xor_sync(0xffffffffu, v, 1);
                v += __shfl_xor_sync(0xffffffffu, v, 2);
                if (tig == 0)
                    part[wn * 128 + wm * 32 + t * 16 + rr * 8 + gr] = v;
            }
        }
        __syncthreads();
        if (tid < 128)
            PpartDst[tid] = part[tid] + part[128 + tid];
    }
}

// ---------------------------------------------------------------------------
// tf32 GEMM wrapper (EPI 0 projections, EPI 1 scores->bf16 S)
// ---------------------------------------------------------------------------
template<int EPI>
__global__ void __launch_bounds__(256, 2) gemm_k(
    const float* __restrict__ Ag, const float* __restrict__ Bg,
    const float* __restrict__ aux, float* __restrict__ Cg,
    int Kdim, int ldA, int ldB, int ldC,
    size_t sA, size_t sB, size_t sC, int auxStride,
    float* __restrict__ Ppart, int roundOut)
{
    const int z = blockIdx.z;
    const int m0 = blockIdx.y * BM;
    const int n0 = blockIdx.x * BN;
    float* pdst = (EPI == 1)
        ? Ppart + ((size_t)z * 8 + blockIdx.x) * SEQ + m0 : nullptr;
    // For EPI==1 Cg is a bf16 buffer; sC is in bf16 elements (cast via char math)
    float* Cz = (EPI == 1)
        ? (float*)((__nv_bfloat16*)Cg + (size_t)z * sC)
        : Cg + (size_t)z * sC;
    gemm_body<EPI>(Ag + (size_t)z * sA, Bg + (size_t)z * sB,
                   aux + (size_t)z * auxStride, Cz,
                   Kdim, ldA, ldB, ldC, m0, n0, pdst, roundOut);
}

// ---------------------------------------------------------------------------
// bf16 PV GEMM: O[M=SEQ, N=HD] = (S @ VT^T) / rowsum, per batch.
// A = S bf16 [SEQ, SEQ] K-major; B = VT bf16 [HD, SEQ] K-major.
// mma.m16n8k16.bf16, 256 threads, 8 warps (4m x 2n), warp tile 32x64.
// ---------------------------------------------------------------------------
__global__ void __launch_bounds__(256, 2) pv_k(
    const __nv_bfloat16* __restrict__ Sg,
    const __nv_bfloat16* __restrict__ VTg,
    const float* __restrict__ P, float* __restrict__ Og)
{
    extern __shared__ float smem[];
    const uint32_t sbase = smem_u32(smem);

    const int z = blockIdx.z;
    const int m0 = blockIdx.y * BM;
    const int n0 = blockIdx.x * BN;
    const __nv_bfloat16* A = Sg  + (size_t)z * SEQ * SEQ + (size_t)m0 * SEQ;
    const __nv_bfloat16* B = VTg + (size_t)z * HD * SEQ + (size_t)n0 * SEQ;
    const float* auxp = P + (size_t)z * 8 * SEQ;
    float* C = Og + (size_t)z * SEQ * HD;

    const int tid  = threadIdx.x;
    const int warp = tid >> 5, lane = tid & 31;
    const int wm = warp >> 1, wn = warp & 1;
    const int gr = lane >> 2, tig = lane & 3;

    float acc[2][8][4];
    #pragma unroll
    for (int t = 0; t < 2; t++)
        #pragma unroll
        for (int j = 0; j < 8; j++)
            #pragma unroll
            for (int q = 0; q < 4; q++) acc[t][j][q] = 0.f;

    // staging: thread -> row r (0..127), 32B half (16 bf16); 2 cp16/operand
    const int r   = tid >> 1;
    const int c0h = (tid & 1) * 16;              // bf16 offset
    const __nv_bfloat16* gA = A + (size_t)r * SEQ + c0h;
    const __nv_bfloat16* gB = B + (size_t)r * SEQ + c0h;
    const uint32_t so = (uint32_t)(r * ST2 + c0h) * 2;   // byte offset

    // ldmatrix lane addresses
    // A 16x16 bf16 tile: lanes 0-7 rows0-7 kseg0; 8-15 rows8-15 kseg0;
    //                    16-23 rows0-7 kseg1; 24-31 rows8-15 kseg1
    const int a_row = (lane & 7) + ((lane >> 3) & 1) * 8;
    const int a_seg = lane >> 4;
    const uint32_t aoff0 = (uint32_t)((wm * 32 + a_row) * ST2) * 2 + a_seg * 16;
    const uint32_t aoff1 = aoff0 + 16 * ST2 * 2;
    // B n16xk16 tile: lanes 0-7 n0-7 kseg0; 8-15 n0-7 kseg1;
    //                 16-23 n8-15 kseg0; 24-31 n8-15 kseg1
    const int b_row = (lane & 7) + (lane >> 4) * 8;
    const int b_seg = (lane >> 3) & 1;
    uint32_t boff[4];
    #pragma unroll
    for (int jb = 0; jb < 4; jb++)
        boff[jb] = (uint32_t)((wn * 64 + jb * 16 + b_row) * ST2) * 2 + b_seg * 16;

    const int KB = SEQ / BK2;   // 32
    auto issue = [&](int kt) {
        const uint32_t st = sbase + (uint32_t)(kt & (STAGES - 1)) * STAGE2_BYTES;
        const int k0 = kt * BK2;
        cp16(st + so, gA + k0);
        cp16(st + so + 16, gA + k0 + 8);
        cp16(st + TILE2_BYTES + so, gB + k0);
        cp16(st + TILE2_BYTES + so + 16, gB + k0 + 8);
    };

    issue(0);
    asm volatile("cp.async.commit_group;" ::: "memory");
    issue(1);
    asm volatile("cp.async.commit_group;" ::: "memory");
    issue(2);
    asm volatile("cp.async.commit_group;" ::: "memory");

    for (int kt = 0; kt < KB; kt++) {
        asm volatile("cp.async.wait_group %0;" :: "n"(STAGES - 2) : "memory");
        __syncthreads();
        if (kt + STAGES - 1 < KB) issue(kt + STAGES - 1);
        asm volatile("cp.async.commit_group;" ::: "memory");

        const uint32_t stA = sbase + (uint32_t)(kt & (STAGES - 1)) * STAGE2_BYTES;
        const uint32_t stB = stA + TILE2_BYTES;
        #pragma unroll
        for (int kk = 0; kk < 2; kk++) {        // two k16 steps per BK2=32
            unsigned af[2][4];
            ldsm4(stA + aoff0 + kk * 32, af[0][0], af[0][1], af[0][2], af[0][3]);
            ldsm4(stA + aoff1 + kk * 32, af[1][0], af[1][1], af[1][2], af[1][3]);
            unsigned bf[4][4];
            #pragma unroll
            for (int jb = 0; jb < 4; jb++)
                ldsm4(stB + boff[jb] + kk * 32,
                      bf[jb][0], bf[jb][1], bf[jb][2], bf[jb][3]);
            #pragma unroll
            for (int j = 0; j < 8; j++) {
                const unsigned* bp = &bf[j >> 1][(j & 1) * 2];
                mma_bf16(acc[0][j], af[0], bp);
                mma_bf16(acc[1][j], af[1], bp);
            }
        }
    }

    // Epilogue: divide by rowsum (from 8 per-n-tile partials, nt ascending)
    #pragma unroll
    for (int t = 0; t < 2; t++) {
        const int r0 = m0 + wm * 32 + t * 16 + gr;
        const int r1 = r0 + 8;
        float l0 = 0.f, l1 = 0.f;
        #pragma unroll
        for (int nt = 0; nt < 8; nt++) {
            l0 += auxp[(nt << 10) + r0];
            l1 += auxp[(nt << 10) + r1];
        }
        const float rv0 = 1.f / l0;
        const float rv1 = 1.f / l1;
        #pragma unroll
        for (int j = 0; j < 8; j++) {
            const int c = n0 + wn * 64 + j * 8 + 2 * tig;
            float2 v0 = {acc[0 + 0][j][0], 0.f};
            (void)v0;
            float2 o0 = {acc[t][j][0] * rv0, acc[t][j][1] * rv0};
            float2 o1 = {acc[t][j][2] * rv1, acc[t][j][3] * rv1};
            *(float2*)&C[(size_t)r0 * HD + c] = o0;
            *(float2*)&C[(size_t)r1 * HD + c] = o1;
        }
    }
}

// ---------------------------------------------------------------------------
// 4-way merged projection: Q/K/V/T2 = A @ {qw,kw,vw,lw}^T + bias
// Q,K outputs tf32-rounded (scores operands); V,T2 left fp32.
// ---------------------------------------------------------------------------
__global__ void __launch_bounds__(256, 2) proj4_k(
    const float* __restrict__ A,
    const float* __restrict__ w0, const float* __restrict__ w1,
    const float* __restrict__ w2, const float* __restrict__ w3,
    const float* __restrict__ b0, const float* __restrict__ b1,
    const float* __restrict__ b2, const float* __restrict__ b3,
    float* __restrict__ c0, float* __restrict__ c1,
    float* __restrict__ c2, float* __restrict__ c3)
{
    const int g  = blockIdx.x >> 1;
    const int n0 = (blockIdx.x & 1) * BN;
    const int m0 = blockIdx.y * BM;
    const float* W    = (g == 0) ? w0 : (g == 1) ? w1 : (g == 2) ? w2 : w3;
    const float* bias = (g == 0) ? b0 : (g == 1) ? b1 : (g == 2) ? b2 : b3;
    float*       C    = (g == 0) ? c0 : (g == 1) ? c1 : (g == 2) ? c2 : c3;
    gemm_body<0>(A, W, bias, C, HD, HD, HD, HD, m0, n0, nullptr, (g < 2) ? 1 : 0);
}

// ---------------------------------------------------------------------------
// Single-launch tf32 rounding of 5 weight tensors + feats.
// ---------------------------------------------------------------------------
constexpr int WN = 3 * HD * HD;          // 196608 floats per weight tensor
constexpr int WB = WN / 1024;            // 192 blocks per weight tensor
constexpr int FB = MTOT * HD / 1024;     // 8192 blocks for feats

__global__ void __launch_bounds__(256) round6_k(
    const float* __restrict__ s0, const float* __restrict__ s1,
    const float* __restrict__ s2, const float* __restrict__ s3,
    const float* __restrict__ s4, const float* __restrict__ s5,
    float* __restrict__ d0, float* __restrict__ d1,
    float* __restrict__ d2, float* __restrict__ d3,
    float* __restrict__ d4, float* __restrict__ d5)
{
    const int b = blockIdx.x;
    const float* src; float* dst; int off;
    if (b < 5 * WB) {
        const int seg = b / WB;
        off = (b - seg * WB) * 1024;
        src = (seg == 0) ? s0 : (seg == 1) ? s1 : (seg == 2) ? s2
            : (seg == 3) ? s3 : s4;
        dst = (seg == 0) ? d0 : (seg == 1) ? d1 : (seg == 2) ? d2
            : (seg == 3) ? d3 : d4;
    } else {
        off = (b - 5 * WB) * 1024;
        src = s5; dst = d5;
    }
    const int i = off + threadIdx.x * 4;
    float4 v = *(const float4*)(src + i);
    v.x = to_tf32(v.x); v.y = to_tf32(v.y);
    v.z = to_tf32(v.z); v.w = to_tf32(v.w);
    *(float4*)(dst + i) = v;
}

// ---------------------------------------------------------------------------
// Per-batch transpose to bf16: X[z*SEQ+n][h] -> Y[z][h][n] (bf16)
// ---------------------------------------------------------------------------
__global__ void __launch_bounds__(256) transpose_k(const float* __restrict__ X,
                                                  __nv_bfloat16* __restrict__ Y)
{
    __shared__ float t[32][33];
    const int z = blockIdx.z, n0 = blockIdx.x * 32, h0 = blockIdx.y * 32;
    const int tx = threadIdx.x & 31, ty = threadIdx.x >> 5;
    #pragma unroll
    for (int i = 0; i < 4; i++) {
        const int rr = ty + 8 * i;
        t[rr][tx] = X[((size_t)z * SEQ + n0 + rr) * HD + h0 + tx];
    }
    __syncthreads();
    #pragma unroll
    for (int i = 0; i < 4; i++) {
        const int rr = ty + 8 * i;
        Y[((size_t)z * HD + h0 + rr) * SEQ + n0 + tx] = __float2bfloat16(t[tx][rr]);
    }
}

// ---------------------------------------------------------------------------
// Y = tf32(relu(LN(X))) rowwise over H=256. One warp per row.
// ---------------------------------------------------------------------------
__global__ void __launch_bounds__(256) relu_ln_k(
    const float* __restrict__ X, const float* __restrict__ G,
    const float* __restrict__ Bt, float* __restrict__ Y)
{
    const int row  = blockIdx.x * 8 + (threadIdx.x >> 5);
    const int lane = threadIdx.x & 31;
    const float4* x4 = reinterpret_cast<const float4*>(X + (size_t)row * HD);
    float4 a = x4[lane], b = x4[lane + 32];

    float s = a.x + a.y + a.z + a.w + b.x + b.y + b.z + b.w;
    s = wsum(s);
    const float mu = s * (1.f / HD);
    a.x -= mu; a.y -= mu; a.z -= mu; a.w -= mu;
    b.x -= mu; b.y -= mu; b.z -= mu; b.w -= mu;
    float q = a.x*a.x + a.y*a.y + a.z*a.z + a.w*a.w
            + b.x*b.x + b.y*b.y + b.z*b.z + b.w*b.w;
    q = wsum(q);
    const float inv = rsqrtf(q * (1.f / HD) + 1e-5f);

    const float4* g4 = reinterpret_cast<const float4*>(G);
    const float4* c4 = reinterpret_cast<const float4*>(Bt);
    float4 g0 = g4[lane], g1 = g4[lane + 32];
    float4 c0 = c4[lane], c1 = c4[lane + 32];

    float4 o0, o1;
    o0.x = to_tf32(fmaxf(a.x * inv * g0.x + c0.x, 0.f));
    o0.y = to_tf32(fmaxf(a.y * inv * g0.y + c0.y, 0.f));
    o0.z = to_tf32(fmaxf(a.z * inv * g0.z + c0.z, 0.f));
    o0.w = to_tf32(fmaxf(a.w * inv * g0.w + c0.w, 0.f));
    o1.x = to_tf32(fmaxf(b.x * inv * g1.x + c1.x, 0.f));
    o1.y = to_tf32(fmaxf(b.y * inv * g1.y + c1.y, 0.f));
    o1.z = to_tf32(fmaxf(b.z * inv * g1.z + c1.z, 0.f));
    o1.w = to_tf32(fmaxf(b.w * inv * g1.w + c1.w, 0.f));

    float4* y4 = reinterpret_cast<float4*>(Y + (size_t)row * HD);
    y4[lane] = o0; y4[lane + 32] = o1;
}

// ---------------------------------------------------------------------------
// Y = LN(Xa) + LN(Xb); doRelu -> relu + tf32 round (intermediate layers).
// ---------------------------------------------------------------------------
__global__ void __launch_bounds__(256) dual_ln_add_k(
    const float* __restrict__ Xa, const float* __restrict__ Xb,
    const float* __restrict__ Ga, const float* __restrict__ Ba,
    const float* __restrict__ Gb, const float* __restrict__ Bb,
    float* __restrict__ Y, int doRelu)
{
    const int row  = blockIdx.x * 8 + (threadIdx.x >> 5);
    const int lane = threadIdx.x & 31;

    const float4* xa4 = reinterpret_cast<const float4*>(Xa + (size_t)row * HD);
    const float4* xb4 = reinterpret_cast<const float4*>(Xb + (size_t)row * HD);
    float4 a0 = xa4[lane], a1 = xa4[lane + 32];
    float4 b0 = xb4[lane], b1 = xb4[lane + 32];

    float sa = a0.x+a0.y+a0.z+a0.w + a1.x+a1.y+a1.z+a1.w;
    float sb = b0.x+b0.y+b0.z+b0.w + b1.x+b1.y+b1.z+b1.w;
    sa = wsum(sa); sb = wsum(sb);
    const float mua = sa * (1.f / HD), mub = sb * (1.f / HD);
    a0.x-=mua; a0.y-=mua; a0.z-=mua; a0.w-=mua;
    a1.x-=mua; a1.y-=mua; a1.z-=mua; a1.w-=mua;
    b0.x-=mub; b0.y-=mub; b0.z-=mub; b0.w-=mub;
    b1.x-=mub; b1.y-=mub; b1.z-=mub; b1.w-=mub;
    float qa = a0.x*a0.x+a0.y*a0.y+a0.z*a0.z+a0.w*a0.w
             + a1.x*a1.x+a1.y*a1.y+a1.z*a1.z+a1.w*a1.w;
    float qb = b0.x*b0.x+b0.y*b0.y+b0.z*b0.z+b0.w*b0.w
             + b1.x*b1.x+b1.y*b1.y+b1.z*b1.z+b1.w*b1.w;
    qa = wsum(qa); qb = wsum(qb);
    const float inva = rsqrtf(qa * (1.f / HD) + 1e-5f);
    const float invb = rsqrtf(qb * (1.f / HD) + 1e-5f);

    const float4* ga4 = reinterpret_cast<const float4*>(Ga);
    const float4* ba4 = reinterpret_cast<const float4*>(Ba);
    const float4* gb4 = reinterpret_cast<const float4*>(Gb);
    const float4* bb4 = reinterpret_cast<const float4*>(Bb);
    float4 ga0 = ga4[lane], ga1 = ga4[lane + 32];
    float4 ca0 = ba4[lane], ca1 = ba4[lane + 32];
    float4 gb0 = gb4[lane], gb1 = gb4[lane + 32];
    float4 cb0 = bb4[lane], cb1 = bb4[lane + 32];

    float4 o0, o1;
    o0.x = (a0.x*inva*ga0.x + ca0.x) + (b0.x*invb*gb0.x + cb0.x);
    o0.y = (a0.y*inva*ga0.y + ca0.y) + (b0.y*invb*gb0.y + cb0.y);
    o0.z = (a0.z*inva*ga0.z + ca0.z) + (b0.z*invb*gb0.z + cb0.z);
    o0.w = (a0.w*inva*ga0.w + ca0.w) + (b0.w*invb*gb0.w + cb0.w);
    o1.x = (a1.x*inva*ga1.x + ca1.x) + (b1.x*invb*gb1.x + cb1.x);
    o1.y = (a1.y*inva*ga1.y + ca1.y) + (b1.y*invb*gb1.y + cb1.y);
    o1.z = (a1.z*inva*ga1.z + ca1.z) + (b1.z*invb*gb1.z + cb1.z);
    o1.w = (a1.w*inva*ga1.w + ca1.w) + (b1.w*invb*gb1.w + cb1.w);
    if (doRelu) {
        o0.x = to_tf32(fmaxf(o0.x, 0.f)); o0.y = to_tf32(fmaxf(o0.y, 0.f));
        o0.z = to_tf32(fmaxf(o0.z, 0.f)); o0.w = to_tf32(fmaxf(o0.w, 0.f));
        o1.x = to_tf32(fmaxf(o1.x, 0.f)); o1.y = to_tf32(fmaxf(o1.y, 0.f));
        o1.z = to_tf32(fmaxf(o1.z, 0.f)); o1.w = to_tf32(fmaxf(o1.w, 0.f));
    }

    float4* y4 = reinterpret_cast<float4*>(Y + (size_t)row * HD);
    y4[lane] = o0; y4[lane + 32] = o1;
}

// ---------------------------------------------------------------------------
// Host launch
// ---------------------------------------------------------------------------
extern "C" void kernel_launch(void* const* d_in, const int* in_sizes, int n_in,
                              void* d_out, int out_size)
{
    (void)in_sizes; (void)n_in; (void)out_size;
    const float* feats   = (const float*)d_in[0];
    const float* masks   = (const float*)d_in[1];
    const float* qw      = (const float*)d_in[2];
    const float* qbias   = (const float*)d_in[3];
    const float* kw      = (const float*)d_in[4];
    const float* kbias   = (const float*)d_in[5];
    const float* vw      = (const float*)d_in[6];
    const float* vbias   = (const float*)d_in[7];
    const float* alng    = (const float*)d_in[8];
    const float* alnb    = (const float*)d_in[9];
    const float* caw     = (const float*)d_in[10];
    const float* cabias  = (const float*)d_in[11];
    const float* calng   = (const float*)d_in[12];
    const float* calnb   = (const float*)d_in[13];
    const float* lw      = (const float*)d_in[14];
    const float* lbias   = (const float*)d_in[15];
    const float* llng    = (const float*)d_in[16];
    const float* llnb    = (const float*)d_in[17];
    float* out = (float*)d_out;

    float *Q, *K, *V, *O, *X1, *T1, *T2, *F, *P, *WR;
    __nv_bfloat16 *VTh, *Sh;
    cudaGetSymbolAddress((void**)&Q,  g_Q);
    cudaGetSymbolAddress((void**)&K,  g_K);
    cudaGetSymbolAddress((void**)&V,  g_V);
    cudaGetSymbolAddress((void**)&VTh, g_VTh);
    cudaGetSymbolAddress((void**)&O,  g_O);
    cudaGetSymbolAddress((void**)&X1, g_X1);
    cudaGetSymbolAddress((void**)&T1, g_T1);
    cudaGetSymbolAddress((void**)&T2, g_T2);
    cudaGetSymbolAddress((void**)&F,  g_F);
    cudaGetSymbolAddress((void**)&Sh, g_Sh);
    cudaGetSymbolAddress((void**)&P,  g_P);
    cudaGetSymbolAddress((void**)&WR, g_WR);

    cudaFuncSetAttribute(gemm_k<0>, cudaFuncAttributeMaxDynamicSharedMemorySize, GEMM_SMEM);
    cudaFuncSetAttribute(gemm_k<1>, cudaFuncAttributeMaxDynamicSharedMemorySize, GEMM_SMEM);
    cudaFuncSetAttribute(pv_k,      cudaFuncAttributeMaxDynamicSharedMemorySize, PV_SMEM);
    cudaFuncSetAttribute(proj4_k,   cudaFuncAttributeMaxDynamicSharedMemorySize, GEMM_SMEM);

    float* qwR = WR + 0 * (size_t)WN;
    float* kwR = WR + 1 * (size_t)WN;
    float* vwR = WR + 2 * (size_t)WN;
    float* cwR = WR + 3 * (size_t)WN;
    float* lwR = WR + 4 * (size_t)WN;

    const dim3 blk(256);
    round6_k<<<dim3(5 * WB + FB), blk>>>(qw, kw, vw, caw, lw, feats,
                                         qwR, kwR, vwR, cwR, lwR, F);

    const dim3 gProj(HD / BN, MTOT / BM, 1);           // (2, 256) for T1
    const dim3 gProj4(8, MTOT / BM, 1);                // (8, 256) merged QKV+T2
    const dim3 gScore(SEQ / BN, SEQ / BM, BATCH);      // (8, 8, 32)
    const dim3 gPV(HD / BN, SEQ / BM, BATCH);          // (2, 8, 32)
    const dim3 gTr(SEQ / 32, HD / 32, BATCH);

    for (int i = 0; i < 3; i++) {
        const size_t wOff = (size_t)i * HD * HD;
        const size_t bOff = (size_t)i * HD;

        proj4_k<<<gProj4, blk, GEMM_SMEM>>>(F,
                                 qwR + wOff, kwR + wOff, vwR + wOff, lwR + wOff,
                                 qbias + bOff, kbias + bOff, vbias + bOff, lbias + bOff,
                                 Q, K, V, T2);

        transpose_k<<<gTr, blk>>>(V, VTh);

        // scores -> bf16 S + fp32 per-tile row partials
        gemm_k<1><<<gScore, blk, GEMM_SMEM>>>(Q, K, masks, (float*)Sh,
                                   HD, HD, HD, SEQ,
                                   (size_t)SEQ * HD, (size_t)SEQ * HD,
                                   (size_t)SEQ * SEQ, SEQ, P, 0);

        // PV: bf16 mma, rowsum folded into epilogue
        pv_k<<<gPV, blk, PV_SMEM>>>(Sh, VTh, P, O);

        relu_ln_k<<<MTOT / 8, blk>>>(O, alng + bOff, alnb + bOff, X1);

        gemm_k<0><<<gProj, blk, GEMM_SMEM>>>(X1, cwR + wOff, cabias + bOff, T1,
                                  HD, HD, HD, HD, 0, 0, 0, 0, nullptr, 0);

        dual_ln_add_k<<<MTOT / 8, blk>>>(T1, T2,
                                         calng + bOff, calnb + bOff,
                                         llng + bOff, llnb + bOff,
                                         (i == 2) ? out : F, (i < 2) ? 1 : 0);
    }
}

// round 16
// speedup vs baseline: 1.1941x; 1.0170x over previous
#include <cuda_runtime.h>
#include <cuda_bf16.h>
#include <cstdint>

#define DEV_INLINE __device__ __forceinline__

// Problem constants
constexpr int BATCH = 32;
constexpr int SEQ   = 1024;
constexpr int HD    = 256;
constexpr int MTOT  = BATCH * SEQ;   // 32768

// tf32 GEMM tiling (NT: C[M,N] = A[M,K] @ B[N,K]^T, K-major operands)
constexpr int BM = 128, BN = 128, BK = 16;
constexpr int ST = 20;                    // padded smem row stride (floats)
constexpr int TILE_WORDS = BM * ST;       // 2560 floats per operand tile
constexpr int STAGES = 4;                 // 3 tile-loads in flight
constexpr int STAGE_BYTES = 2 * TILE_WORDS * 4;       // A+B per stage, 20480 B
constexpr int GEMM_SMEM = STAGES * STAGE_BYTES;       // 81920 B dynamic
constexpr int PROJ_SMEM = GEMM_SMEM + 2048;           // + u,v vectors (512 f)

// bf16 PV GEMM tiling
constexpr int BK2 = 32;
constexpr int ST2 = 40;
constexpr int TILE2_BYTES = 128 * ST2 * 2;            // 10240 B per operand
constexpr int STAGE2_BYTES = 2 * TILE2_BYTES;         // 20480 B
constexpr int PV_SMEM = STAGES * STAGE2_BYTES;        // 81920 B dynamic

// ---------------------------------------------------------------------------
// Scratch (device globals: the sanctioned no-alloc path)
// ---------------------------------------------------------------------------
__device__ float g_A [(size_t)MTOT * HD];              // A' = F @ W
__device__ float g_V [(size_t)MTOT * HD];
__device__ __nv_bfloat16 g_VTh[(size_t)MTOT * HD];     // per-batch V^T, bf16
__device__ float g_O [(size_t)MTOT * HD];
__device__ float g_X1[(size_t)MTOT * HD];
__device__ float g_T1[(size_t)MTOT * HD];
__device__ float g_T2[(size_t)MTOT * HD];
__device__ float g_F [(size_t)MTOT * HD];              // rounded features
__device__ __nv_bfloat16 g_Sh[(size_t)BATCH * SEQ * SEQ];  // 64 MB exp(scores)
__device__ float g_P [(size_t)BATCH * 8 * SEQ];        // per n-tile partial sums
__device__ float g_WR[(size_t)3 * 3 * HD * HD];        // rounded weights v,ca,l
__device__ float g_Wt[(size_t)3 * HD * HD];            // tf32 W^T per layer
__device__ float g_UV[(size_t)3 * 2 * HD];             // u,v per layer
__device__ float g_Cv[4];                              // qb.kb per layer
__device__ float g_G [(size_t)MTOT];                   // F.u  (col bias term)
__device__ float g_H [(size_t)MTOT];                   // F.v  (row bias term)
__device__ float g_zero[HD];                           // zero bias

// ---------------------------------------------------------------------------
// Helpers
// ---------------------------------------------------------------------------
DEV_INLINE float to_tf32(float x) {
    unsigned u;
    asm("cvt.rna.tf32.f32 %0, %1;" : "=r"(u) : "f"(x));
    return __uint_as_float(u);
}

DEV_INLINE void mma_tf32(float c[4], const unsigned a[4], const unsigned b[2]) {
    asm volatile(
        "mma.sync.aligned.m16n8k8.row.col.f32.tf32.tf32.f32 "
        "{%0,%1,%2,%3}, {%4,%5,%6,%7}, {%8,%9}, {%0,%1,%2,%3};"
        : "+f"(c[0]), "+f"(c[1]), "+f"(c[2]), "+f"(c[3])
        : "r"(a[0]), "r"(a[1]), "r"(a[2]), "r"(a[3]), "r"(b[0]), "r"(b[1]));
}

DEV_INLINE void mma_bf16(float c[4], const unsigned a[4], const unsigned b[2]) {
    asm volatile(
        "mma.sync.aligned.m16n8k16.row.col.f32.bf16.bf16.f32 "
        "{%0,%1,%2,%3}, {%4,%5,%6,%7}, {%8,%9}, {%0,%1,%2,%3};"
        : "+f"(c[0]), "+f"(c[1]), "+f"(c[2]), "+f"(c[3])
        : "r"(a[0]), "r"(a[1]), "r"(a[2]), "r"(a[3]), "r"(b[0]), "r"(b[1]));
}

DEV_INLINE void ldsm4(uint32_t addr, unsigned& r0, unsigned& r1,
                      unsigned& r2, unsigned& r3) {
    asm volatile("ldmatrix.sync.aligned.m8n8.x4.shared.b16 {%0,%1,%2,%3}, [%4];"
                 : "=r"(r0), "=r"(r1), "=r"(r2), "=r"(r3) : "r"(addr));
}

DEV_INLINE uint32_t smem_u32(const void* p) {
    uint32_t a;
    asm("{ .reg .u64 t; cvta.to.shared.u64 t, %1; cvt.u32.u64 %0, t; }" : "=r"(a) : "l"(p));
    return a;
}

DEV_INLINE void cp16(uint32_t dst, const void* src) {
    asm volatile("cp.async.cg.shared.global [%0], [%1], 16;"
                 :: "r"(dst), "l"(src) : "memory");
}

DEV_INLINE float wsum(float v) {
    #pragma unroll
    for (int o = 16; o; o >>= 1) v += __shfl_xor_sync(0xffffffffu, v, o);
    return v;
}

// ---------------------------------------------------------------------------
// tf32 GEMM body (fp32 K-major operands, pre-rounded to tf32).
//   EPI 0: C = A@B^T + bias[col]; roundOut -> tf32-round stores
//   EPI 1: scores with rank-1 bias terms: raw = x + Hv[r] + Gv[c] + cv;
//          store bf16(exp(raw*SCALE + maskbias)); emit per-row partials
//   GH 1 : additionally accumulate G=F.u, H=F.v from staged A tiles
//          (u,v live in smem past the pipeline ring; n0==0 blocks write)
// ---------------------------------------------------------------------------
template<int EPI, int GH>
DEV_INLINE void gemm_body(
    const float* __restrict__ A, const float* __restrict__ B,
    const float* __restrict__ auxp, float* __restrict__ C,
    int Kdim, int ldA, int ldB, int ldC,
    int m0, int n0, float* __restrict__ PpartDst, int roundOut,
    const float* __restrict__ UVg, float* __restrict__ Gout,
    float* __restrict__ Hout,
    const float* __restrict__ Gv, const float* __restrict__ Hv,
    const float* __restrict__ Cp)
{
    extern __shared__ float smem[];
    const uint32_t sbase = smem_u32(smem);
    float* usm = smem + GEMM_SMEM / 4;     // u[256], v[256] (GH only)

    const int tid  = threadIdx.x;
    const int warp = tid >> 5, lane = tid & 31;
    const int wm = warp >> 1, wn = warp & 1;
    const int gr = lane >> 2, tig = lane & 3;

    float acc[2][8][4];
    #pragma unroll
    for (int t = 0; t < 2; t++)
        #pragma unroll
        for (int j = 0; j < 8; j++)
            #pragma unroll
            for (int q = 0; q < 4; q++) acc[t][j][q] = 0.f;

    const int ar = tid >> 2;
    const int ac = (tid & 3) * 4;
    const float* gA0 = A + (size_t)(m0 + ar) * ldA + ac;
    const float* gA1 = gA0 + (size_t)64 * ldA;
    const float* gB0 = B + (size_t)(n0 + ar) * ldB + ac;
    const float* gB1 = gB0 + (size_t)64 * ldB;
    const uint32_t so = (uint32_t)(ar * ST + ac) * 4;

    const int la_row = lane & 15;
    const int la_k   = (lane >> 4) * 4;
    const int lb_n   = (lane & 7) + ((lane >> 4) << 3);
    const int lb_k   = ((lane >> 3) & 1) * 4;
    const uint32_t aoff0 = (uint32_t)((wm * 32 + la_row) * ST + la_k) * 4;
    const uint32_t aoff1 = aoff0 + 16 * ST * 4;
    uint32_t boff[4];
    #pragma unroll
    for (int jb = 0; jb < 4; jb++)
        boff[jb] = (uint32_t)((wn * 64 + jb * 16 + lb_n) * ST + lb_k) * 4;

    float ga0 = 0.f, ha0 = 0.f, ga1 = 0.f, ha1 = 0.f;
    if (GH) {
        for (int i = tid; i < 2 * HD; i += 256) usm[i] = UVg[i];
    }

    const int KB = Kdim / BK;
    auto issue = [&](int kt) {
        const uint32_t st = sbase + (uint32_t)(kt & (STAGES - 1)) * STAGE_BYTES;
        const int k0 = kt * BK;
        cp16(st + so, gA0 + k0);
        cp16(st + so + 64 * ST * 4, gA1 + k0);
        cp16(st + TILE_WORDS * 4 + so, gB0 + k0);
        cp16(st + TILE_WORDS * 4 + so + 64 * ST * 4, gB1 + k0);
    };

    issue(0);
    asm volatile("cp.async.commit_group;" ::: "memory");
    issue(1);
    asm volatile("cp.async.commit_group;" ::: "memory");
    issue(2);
    asm volatile("cp.async.commit_group;" ::: "memory");

    for (int kt = 0; kt < KB; kt++) {
        asm volatile("cp.async.wait_group %0;" :: "n"(STAGES - 2) : "memory");
        __syncthreads();
        if (kt + STAGES - 1 < KB) issue(kt + STAGES - 1);
        asm volatile("cp.async.commit_group;" ::: "memory");

        if (GH) {
            const float* sp = smem + (size_t)(kt & (STAGES - 1)) * (STAGE_BYTES / 4);
            const float4 fa = *(const float4*)(sp + ar * ST + ac);
            const float4 fb = *(const float4*)(sp + (ar + 64) * ST + ac);
            const float4 u4 = *(const float4*)(usm + kt * BK + ac);
            const float4 v4 = *(const float4*)(usm + HD + kt * BK + ac);
            ga0 += fa.x*u4.x + fa.y*u4.y + fa.z*u4.z + fa.w*u4.w;
            ha0 += fa.x*v4.x + fa.y*v4.y + fa.z*v4.z + fa.w*v4.w;
            ga1 += fb.x*u4.x + fb.y*u4.y + fb.z*u4.z + fb.w*u4.w;
            ha1 += fb.x*v4.x + fb.y*v4.y + fb.z*v4.z + fb.w*v4.w;
        }

        const uint32_t stA = sbase + (uint32_t)(kt & (STAGES - 1)) * STAGE_BYTES;
        const uint32_t stB = stA + TILE_WORDS * 4;
        #pragma unroll
        for (int kk = 0; kk < 2; kk++) {
            unsigned af[2][4];
            ldsm4(stA + aoff0 + kk * 32, af[0][0], af[0][1], af[0][2], af[0][3]);
            ldsm4(stA + aoff1 + kk * 32, af[1][0], af[1][1], af[1][2], af[1][3]);
            unsigned bf[4][4];
            #pragma unroll
            for (int jb = 0; jb < 4; jb++)
                ldsm4(stB + boff[jb] + kk * 32,
                      bf[jb][0], bf[jb][1], bf[jb][2], bf[jb][3]);
            #pragma unroll
            for (int j = 0; j < 8; j++) {
                const unsigned* bp = &bf[j >> 1][(j & 1) * 2];
                mma_tf32(acc[0][j], af[0], bp);
                mma_tf32(acc[1][j], af[1], bp);
            }
        }
    }

    if (GH) {
        #pragma unroll
        for (int o = 1; o <= 2; o <<= 1) {
            ga0 += __shfl_xor_sync(0xffffffffu, ga0, o);
            ha0 += __shfl_xor_sync(0xffffffffu, ha0, o);
            ga1 += __shfl_xor_sync(0xffffffffu, ga1, o);
            ha1 += __shfl_xor_sync(0xffffffffu, ha1, o);
        }
        if (n0 == 0 && (lane & 3) == 0) {
            Gout[m0 + ar] = ga0;      Hout[m0 + ar] = ha0;
            Gout[m0 + ar + 64] = ga1; Hout[m0 + ar + 64] = ha1;
        }
    }

    // Epilogue
    const float SCALE = 0.0625f;  // 1/sqrt(256)
    float rs[2][2];
    rs[0][0] = rs[0][1] = rs[1][0] = rs[1][1] = 0.f;
    __nv_bfloat16* Cb = reinterpret_cast<__nv_bfloat16*>(C);
    const float cv = (EPI == 1) ? Cp[0] : 0.f;

    #pragma unroll
    for (int t = 0; t < 2; t++) {
        const int r0 = m0 + wm * 32 + t * 16 + gr;
        const int r1 = r0 + 8;
        float mq0 = 0.f, mq1 = 0.f, hr0 = 0.f, hr1 = 0.f;
        if (EPI == 1) {
            mq0 = auxp[r0]; mq1 = auxp[r1];
            hr0 = Hv[r0] + cv; hr1 = Hv[r1] + cv;
        }
        #pragma unroll
        for (int j = 0; j < 8; j++) {
            const int c = n0 + wn * 64 + j * 8 + 2 * tig;
            float x0 = acc[t][j][0], x1 = acc[t][j][1];
            float x2 = acc[t][j][2], x3 = acc[t][j][3];
            if (EPI == 0) {
                const float b0 = auxp[c], b1 = auxp[c + 1];
                float y0 = x0 + b0, y1 = x1 + b1;
                float y2 = x2 + b0, y3 = x3 + b1;
                if (roundOut) {
                    y0 = to_tf32(y0); y1 = to_tf32(y1);
                    y2 = to_tf32(y2); y3 = to_tf32(y3);
                }
                float2 v0 = {y0, y1};
                float2 v1 = {y2, y3};
                *(float2*)&C[(size_t)r0 * ldC + c] = v0;
                *(float2*)&C[(size_t)r1 * ldC + c] = v1;
            } else {
                // raw score = x + h_row + g_col + c ; then scale + mask bias
                const float mc0 = auxp[c], mc1 = auxp[c + 1];
                const float gc0 = Gv[c], gc1 = Gv[c + 1];
                const float s00 = x0 + hr0 + gc0, s01 = x1 + hr0 + gc1;
                const float s10 = x2 + hr1 + gc0, s11 = x3 + hr1 + gc1;
                float e00, e01, e10, e11;
                if (mq0 > 0.5f) {
                    e00 = (mc0 > 0.5f) ? __expf(s00 * SCALE + 1.f) : 0.f;
                    e01 = (mc1 > 0.5f) ? __expf(s01 * SCALE + 1.f) : 0.f;
                } else {
                    e00 = __expf(s00 * SCALE);
                    e01 = __expf(s01 * SCALE);
                }
                if (mq1 > 0.5f) {
                    e10 = (mc0 > 0.5f) ? __expf(s10 * SCALE + 1.f) : 0.f;
                    e11 = (mc1 > 0.5f) ? __expf(s11 * SCALE + 1.f) : 0.f;
                } else {
                    e10 = __expf(s10 * SCALE);
                    e11 = __expf(s11 * SCALE);
                }
                __nv_bfloat16 h00 = __float2bfloat16(e00);
                __nv_bfloat16 h01 = __float2bfloat16(e01);
                __nv_bfloat16 h10 = __float2bfloat16(e10);
                __nv_bfloat16 h11 = __float2bfloat16(e11);
                rs[t][0] += __bfloat162float(h00) + __bfloat162float(h01);
                rs[t][1] += __bfloat162float(h10) + __bfloat162float(h11);
                __nv_bfloat162 p0; p0.x = h00; p0.y = h01;
                __nv_bfloat162 p1; p1.x = h10; p1.y = h11;
                *(__nv_bfloat162*)&Cb[(size_t)r0 * ldC + c] = p0;
                *(__nv_bfloat162*)&Cb[(size_t)r1 * ldC + c] = p1;
            }
        }
    }

    if (EPI == 1) {
        asm volatile("cp.async.wait_group 0;" ::: "memory");
        __syncthreads();
        float* part = smem;
        #pragma unroll
        for (int t = 0; t < 2; t++) {
            #pragma unroll
            for (int rr = 0; rr < 2; rr++) {
                float v = rs[t][rr];
                v += __shfl_xor_sync(0xffffffffu, v, 1);
                v += __shfl_xor_sync(0xffffffffu, v, 2);
                if (tig == 0)
                    part[wn * 128 + wm * 32 + t * 16 + rr * 8 + gr] = v;
            }
        }
        __syncthreads();
        if (tid < 128)
            PpartDst[tid] = part[tid] + part[128 + tid];
    }
}

// ---------------------------------------------------------------------------
// tf32 GEMM wrapper (EPI 0 = T1 projection; EPI 1 = scores -> bf16 S)
// ---------------------------------------------------------------------------
template<int EPI>
__global__ void __launch_bounds__(256, 2) gemm_k(
    const float* __restrict__ Ag, const float* __restrict__ Bg,
    const float* __restrict__ aux, float* __restrict__ Cg,
    int Kdim, int ldA, int ldB, int ldC,
    size_t sA, size_t sB, size_t sC, int auxStride,
    float* __restrict__ Ppart, int roundOut,
    const float* __restrict__ G, const float* __restrict__ H,
    const float* __restrict__ Cp)
{
    const int z = blockIdx.z;
    const int m0 = blockIdx.y * BM;
    const int n0 = blockIdx.x * BN;
    float* pdst = (EPI == 1)
        ? Ppart + ((size_t)z * 8 + blockIdx.x) * SEQ + m0 : nullptr;
    float* Cz = (EPI == 1)
        ? (float*)((__nv_bfloat16*)Cg + (size_t)z * sC)
        : Cg + (size_t)z * sC;
    gemm_body<EPI, 0>(Ag + (size_t)z * sA, Bg + (size_t)z * sB,
                      aux + (size_t)z * auxStride, Cz,
                      Kdim, ldA, ldB, ldC, m0, n0, pdst, roundOut,
                      nullptr, nullptr, nullptr,
                      (EPI == 1) ? G + (size_t)z * SEQ : nullptr,
                      (EPI == 1) ? H + (size_t)z * SEQ : nullptr, Cp);
}

// ---------------------------------------------------------------------------
// 3-way merged projection: A' = F@Wt^T (round, +G/H), V, T2.
// grid (6, 256): blockIdx.x>>1 selects matrix, &1 selects n-half.
// ---------------------------------------------------------------------------
__global__ void __launch_bounds__(256, 2) proj3_k(
    const float* __restrict__ Fm,
    const float* __restrict__ Wt, const float* __restrict__ vwR,
    const float* __restrict__ lwR,
    const float* __restrict__ vb, const float* __restrict__ lb,
    float* __restrict__ Ap, float* __restrict__ V, float* __restrict__ T2,
    const float* __restrict__ UVl, float* __restrict__ G,
    float* __restrict__ H, const float* __restrict__ zero)
{
    const int g  = blockIdx.x >> 1;
    const int n0 = (blockIdx.x & 1) * BN;
    const int m0 = blockIdx.y * BM;
    if (g == 0)
        gemm_body<0, 1>(Fm, Wt, zero, Ap, HD, HD, HD, HD, m0, n0,
                        nullptr, 1, UVl, G, H, nullptr, nullptr, nullptr);
    else if (g == 1)
        gemm_body<0, 0>(Fm, vwR, vb, V, HD, HD, HD, HD, m0, n0,
                        nullptr, 0, nullptr, nullptr, nullptr,
                        nullptr, nullptr, nullptr);
    else
        gemm_body<0, 0>(Fm, lwR, lb, T2, HD, HD, HD, HD, m0, n0,
                        nullptr, 0, nullptr, nullptr, nullptr,
                        nullptr, nullptr, nullptr);
}

// ---------------------------------------------------------------------------
// bf16 PV GEMM: O = (S @ VT^T) / rowsum, per batch.  (unchanged from R14)
// ---------------------------------------------------------------------------
__global__ void __launch_bounds__(256, 2) pv_k(
    const __nv_bfloat16* __restrict__ Sg,
    const __nv_bfloat16* __restrict__ VTg,
    const float* __restrict__ P, float* __restrict__ Og)
{
    extern __shared__ float smem[];
    const uint32_t sbase = smem_u32(smem);

    const int z = blockIdx.z;
    const int m0 = blockIdx.y * BM;
    const int n0 = blockIdx.x * BN;
    const __nv_bfloat16* A = Sg  + (size_t)z * SEQ * SEQ + (size_t)m0 * SEQ;
    const __nv_bfloat16* B = VTg + (size_t)z * HD * SEQ + (size_t)n0 * SEQ;
    const float* auxp = P + (size_t)z * 8 * SEQ;
    float* C = Og + (size_t)z * SEQ * HD;

    const int tid  = threadIdx.x;
    const int warp = tid >> 5, lane = tid & 31;
    const int wm = warp >> 1, wn = warp & 1;
    const int gr = lane >> 2, tig = lane & 3;

    float acc[2][8][4];
    #pragma unroll
    for (int t = 0; t < 2; t++)
        #pragma unroll
        for (int j = 0; j < 8; j++)
            #pragma unroll
            for (int q = 0; q < 4; q++) acc[t][j][q] = 0.f;

    const int r   = tid >> 1;
    const int c0h = (tid & 1) * 16;
    const __nv_bfloat16* gA = A + (size_t)r * SEQ + c0h;
    const __nv_bfloat16* gB = B + (size_t)r * SEQ + c0h;
    const uint32_t so = (uint32_t)(r * ST2 + c0h) * 2;

    const int a_row = (lane & 7) + ((lane >> 3) & 1) * 8;
    const int a_seg = lane >> 4;
    const uint32_t aoff0 = (uint32_t)((wm * 32 + a_row) * ST2) * 2 + a_seg * 16;
    const uint32_t aoff1 = aoff0 + 16 * ST2 * 2;
    const int b_row = (lane & 7) + (lane >> 4) * 8;
    const int b_seg = (lane >> 3) & 1;
    uint32_t boff[4];
    #pragma unroll
    for (int jb = 0; jb < 4; jb++)
        boff[jb] = (uint32_t)((wn * 64 + jb * 16 + b_row) * ST2) * 2 + b_seg * 16;

    const int KB = SEQ / BK2;   // 32
    auto issue = [&](int kt) {
        const uint32_t st = sbase + (uint32_t)(kt & (STAGES - 1)) * STAGE2_BYTES;
        const int k0 = kt * BK2;
        cp16(st + so, gA + k0);
        cp16(st + so + 16, gA + k0 + 8);
        cp16(st + TILE2_BYTES + so, gB + k0);
        cp16(st + TILE2_BYTES + so + 16, gB + k0 + 8);
    };

    issue(0);
    asm volatile("cp.async.commit_group;" ::: "memory");
    issue(1);
    asm volatile("cp.async.commit_group;" ::: "memory");
    issue(2);
    asm volatile("cp.async.commit_group;" ::: "memory");

    for (int kt = 0; kt < KB; kt++) {
        asm volatile("cp.async.wait_group %0;" :: "n"(STAGES - 2) : "memory");
        __syncthreads();
        if (kt + STAGES - 1 < KB) issue(kt + STAGES - 1);
        asm volatile("cp.async.commit_group;" ::: "memory");

        const uint32_t stA = sbase + (uint32_t)(kt & (STAGES - 1)) * STAGE2_BYTES;
        const uint32_t stB = stA + TILE2_BYTES;
        #pragma unroll
        for (int kk = 0; kk < 2; kk++) {
            unsigned af[2][4];
            ldsm4(stA + aoff0 + kk * 32, af[0][0], af[0][1], af[0][2], af[0][3]);
            ldsm4(stA + aoff1 + kk * 32, af[1][0], af[1][1], af[1][2], af[1][3]);
            unsigned bf[4][4];
            #pragma unroll
            for (int jb = 0; jb < 4; jb++)
                ldsm4(stB + boff[jb] + kk * 32,
                      bf[jb][0], bf[jb][1], bf[jb][2], bf[jb][3]);
            #pragma unroll
            for (int j = 0; j < 8; j++) {
                const unsigned* bp = &bf[j >> 1][(j & 1) * 2];
                mma_bf16(acc[0][j], af[0], bp);
                mma_bf16(acc[1][j], af[1], bp);
            }
        }
    }

    #pragma unroll
    for (int t = 0; t < 2; t++) {
        const int r0 = m0 + wm * 32 + t * 16 + gr;
        const int r1 = r0 + 8;
        float l0 = 0.f, l1 = 0.f;
        #pragma unroll
        for (int nt = 0; nt < 8; nt++) {
            l0 += auxp[(nt << 10) + r0];
            l1 += auxp[(nt << 10) + r1];
        }
        const float rv0 = 1.f / l0;
        const float rv1 = 1.f / l1;
        #pragma unroll
        for (int j = 0; j < 8; j++) {
            const int c = n0 + wn * 64 + j * 8 + 2 * tig;
            float2 o0 = {acc[t][j][0] * rv0, acc[t][j][1] * rv0};
            float2 o1 = {acc[t][j][2] * rv1, acc[t][j][3] * rv1};
            *(float2*)&C[(size_t)r0 * HD + c] = o0;
            *(float2*)&C[(size_t)r1 * HD + c] = o1;
        }
    }
}

// ---------------------------------------------------------------------------
// prep: per layer l: Wt[h2][h1] = sum_a kw[a][h2]*qw[a][h1] (tf32-rounded),
//       u[h] = sum_a kw[a][h]*qb[a], v[h] = sum_a qw[a][h]*kb[a], c = qb.kb
// grid 775 blocks x 256 threads.
// ---------------------------------------------------------------------------
__global__ void __launch_bounds__(256) prep_k(
    const float* __restrict__ qw, const float* __restrict__ kw,
    const float* __restrict__ qb, const float* __restrict__ kb,
    float* __restrict__ Wt, float* __restrict__ UV, float* __restrict__ Cv)
{
    const int b = blockIdx.x;
    if (b < 768) {
        const int l = b >> 8, h2 = b & 255;
        const float* qwl = qw + (size_t)l * HD * HD;
        const float* kwl = kw + (size_t)l * HD * HD;
        const int h1 = threadIdx.x;
        float acc = 0.f;
        for (int a = 0; a < HD; a++)
            acc += kwl[a * HD + h2] * qwl[a * HD + h1];
        Wt[(size_t)l * HD * HD + h2 * HD + h1] = to_tf32(acc);
    } else if (b < 774) {
        const int idx = b - 768, l = idx >> 1, s = idx & 1;
        const int h = threadIdx.x;
        const float* w  = ((s == 0) ? kw : qw) + (size_t)l * HD * HD;
        const float* bb = ((s == 0) ? qb : kb) + (size_t)l * HD;
        float acc = 0.f;
        for (int a = 0; a < HD; a++)
            acc += w[a * HD + h] * bb[a];
        UV[(size_t)l * 2 * HD + s * HD + h] = acc;
    } else {
        const int w = threadIdx.x >> 5, lane = threadIdx.x & 31;
        if (w < 3) {
            float acc = 0.f;
            for (int a = lane; a < HD; a += 32)
                acc += qb[w * HD + a] * kb[w * HD + a];
            acc = wsum(acc);
            if (lane == 0) Cv[w] = acc;
        }
    }
}

// ---------------------------------------------------------------------------
// Single-launch tf32 rounding of 3 weight tensors + feats.
// ---------------------------------------------------------------------------
constexpr int WN = 3 * HD * HD;          // 196608 floats per weight tensor
constexpr int WB = WN / 1024;            // 192 blocks per weight tensor
constexpr int FB = MTOT * HD / 1024;     // 8192 blocks for feats

__global__ void __launch_bounds__(256) round4_k(
    const float* __restrict__ s0, const float* __restrict__ s1,
    const float* __restrict__ s2, const float* __restrict__ s3,
    float* __restrict__ d0, float* __restrict__ d1,
    float* __restrict__ d2, float* __restrict__ d3)
{
    const int b = blockIdx.x;
    const float* src; float* dst; int off;
    if (b < 3 * WB) {
        const int seg = b / WB;
        off = (b - seg * WB) * 1024;
        src = (seg == 0) ? s0 : (seg == 1) ? s1 : s2;
        dst = (seg == 0) ? d0 : (seg == 1) ? d1 : d2;
    } else {
        off = (b - 3 * WB) * 1024;
        src = s3; dst = d3;
    }
    const int i = off + threadIdx.x * 4;
    float4 v = *(const float4*)(src + i);
    v.x = to_tf32(v.x); v.y = to_tf32(v.y);
    v.z = to_tf32(v.z); v.w = to_tf32(v.w);
    *(float4*)(dst + i) = v;
}

// ---------------------------------------------------------------------------
// Per-batch transpose to bf16: X[z*SEQ+n][h] -> Y[z][h][n]
// ---------------------------------------------------------------------------
__global__ void __launch_bounds__(256) transpose_k(const float* __restrict__ X,
                                                  __nv_bfloat16* __restrict__ Y)
{
    __shared__ float t[32][33];
    const int z = blockIdx.z, n0 = blockIdx.x * 32, h0 = blockIdx.y * 32;
    const int tx = threadIdx.x & 31, ty = threadIdx.x >> 5;
    #pragma unroll
    for (int i = 0; i < 4; i++) {
        const int rr = ty + 8 * i;
        t[rr][tx] = X[((size_t)z * SEQ + n0 + rr) * HD + h0 + tx];
    }
    __syncthreads();
    #pragma unroll
    for (int i = 0; i < 4; i++) {
        const int rr = ty + 8 * i;
        Y[((size_t)z * HD + h0 + rr) * SEQ + n0 + tx] = __float2bfloat16(t[tx][rr]);
    }
}

// ---------------------------------------------------------------------------
// Y = tf32(relu(LN(X))) rowwise over H=256. One warp per row.
// ---------------------------------------------------------------------------
__global__ void __launch_bounds__(256) relu_ln_k(
    const float* __restrict__ X, const float* __restrict__ G,
    const float* __restrict__ Bt, float* __restrict__ Y)
{
    const int row  = blockIdx.x * 8 + (threadIdx.x >> 5);
    const int lane = threadIdx.x & 31;
    const float4* x4 = reinterpret_cast<const float4*>(X + (size_t)row * HD);
    float4 a = x4[lane], b = x4[lane + 32];

    float s = a.x + a.y + a.z + a.w + b.x + b.y + b.z + b.w;
    s = wsum(s);
    const float mu = s * (1.f / HD);
    a.x -= mu; a.y -= mu; a.z -= mu; a.w -= mu;
    b.x -= mu; b.y -= mu; b.z -= mu; b.w -= mu;
    float q = a.x*a.x + a.y*a.y + a.z*a.z + a.w*a.w
            + b.x*b.x + b.y*b.y + b.z*b.z + b.w*b.w;
    q = wsum(q);
    const float inv = rsqrtf(q * (1.f / HD) + 1e-5f);

    const float4* g4 = reinterpret_cast<const float4*>(G);
    const float4* c4 = reinterpret_cast<const float4*>(Bt);
    float4 g0 = g4[lane], g1 = g4[lane + 32];
    float4 c0 = c4[lane], c1 = c4[lane + 32];

    float4 o0, o1;
    o0.x = to_tf32(fmaxf(a.x * inv * g0.x + c0.x, 0.f));
    o0.y = to_tf32(fmaxf(a.y * inv * g0.y + c0.y, 0.f));
    o0.z = to_tf32(fmaxf(a.z * inv * g0.z + c0.z, 0.f));
    o0.w = to_tf32(fmaxf(a.w * inv * g0.w + c0.w, 0.f));
    o1.x = to_tf32(fmaxf(b.x * inv * g1.x + c1.x, 0.f));
    o1.y = to_tf32(fmaxf(b.y * inv * g1.y + c1.y, 0.f));
    o1.z = to_tf32(fmaxf(b.z * inv * g1.z + c1.z, 0.f));
    o1.w = to_tf32(fmaxf(b.w * inv * g1.w + c1.w, 0.f));

    float4* y4 = reinterpret_cast<float4*>(Y + (size_t)row * HD);
    y4[lane] = o0; y4[lane + 32] = o1;
}

// ---------------------------------------------------------------------------
// Y = LN(Xa) + LN(Xb); doRelu -> relu + tf32 round (intermediate layers).
// ---------------------------------------------------------------------------
__global__ void __launch_bounds__(256) dual_ln_add_k(
    const float* __restrict__ Xa, const float* __restrict__ Xb,
    const float* __restrict__ Ga, const float* __restrict__ Ba,
    const float* __restrict__ Gb, const float* __restrict__ Bb,
    float* __restrict__ Y, int doRelu)
{
    const int row  = blockIdx.x * 8 + (threadIdx.x >> 5);
    const int lane = threadIdx.x & 31;

    const float4* xa4 = reinterpret_cast<const float4*>(Xa + (size_t)row * HD);
    const float4* xb4 = reinterpret_cast<const float4*>(Xb + (size_t)row * HD);
    float4 a0 = xa4[lane], a1 = xa4[lane + 32];
    float4 b0 = xb4[lane], b1 = xb4[lane + 32];

    float sa = a0.x+a0.y+a0.z+a0.w + a1.x+a1.y+a1.z+a1.w;
    float sb = b0.x+b0.y+b0.z+b0.w + b1.x+b1.y+b1.z+b1.w;
    sa = wsum(sa); sb = wsum(sb);
    const float mua = sa * (1.f / HD), mub = sb * (1.f / HD);
    a0.x-=mua; a0.y-=mua; a0.z-=mua; a0.w-=mua;
    a1.x-=mua; a1.y-=mua; a1.z-=mua; a1.w-=mua;
    b0.x-=mub; b0.y-=mub; b0.z-=mub; b0.w-=mub;
    b1.x-=mub; b1.y-=mub; b1.z-=mub; b1.w-=mub;
    float qa = a0.x*a0.x+a0.y*a0.y+a0.z*a0.z+a0.w*a0.w
             + a1.x*a1.x+a1.y*a1.y+a1.z*a1.z+a1.w*a1.w;
    float qb = b0.x*b0.x+b0.y*b0.y+b0.z*b0.z+b0.w*b0.w
             + b1.x*b1.x+b1.y*b1.y+b1.z*b1.z+b1.w*b1.w;
    qa = wsum(qa); qb = wsum(qb);
    const float inva = rsqrtf(qa * (1.f / HD) + 1e-5f);
    const float invb = rsqrtf(qb * (1.f / HD) + 1e-5f);

    const float4* ga4 = reinterpret_cast<const float4*>(Ga);
    const float4* ba4 = reinterpret_cast<const float4*>(Ba);
    const float4* gb4 = reinterpret_cast<const float4*>(Gb);
    const float4* bb4 = reinterpret_cast<const float4*>(Bb);
    float4 ga0 = ga4[lane], ga1 = ga4[lane + 32];
    float4 ca0 = ba4[lane], ca1 = ba4[lane + 32];
    float4 gb0 = gb4[lane], gb1 = gb4[lane + 32];
    float4 cb0 = bb4[lane], cb1 = bb4[lane + 32];

    float4 o0, o1;
    o0.x = (a0.x*inva*ga0.x + ca0.x) + (b0.x*invb*gb0.x + cb0.x);
    o0.y = (a0.y*inva*ga0.y + ca0.y) + (b0.y*invb*gb0.y + cb0.y);
    o0.z = (a0.z*inva*ga0.z + ca0.z) + (b0.z*invb*gb0.z + cb0.z);
    o0.w = (a0.w*inva*ga0.w + ca0.w) + (b0.w*invb*gb0.w + cb0.w);
    o1.x = (a1.x*inva*ga1.x + ca1.x) + (b1.x*invb*gb1.x + cb1.x);
    o1.y = (a1.y*inva*ga1.y + ca1.y) + (b1.y*invb*gb1.y + cb1.y);
    o1.z = (a1.z*inva*ga1.z + ca1.z) + (b1.z*invb*gb1.z + cb1.z);
    o1.w = (a1.w*inva*ga1.w + ca1.w) + (b1.w*invb*gb1.w + cb1.w);
    if (doRelu) {
        o0.x = to_tf32(fmaxf(o0.x, 0.f)); o0.y = to_tf32(fmaxf(o0.y, 0.f));
        o0.z = to_tf32(fmaxf(o0.z, 0.f)); o0.w = to_tf32(fmaxf(o0.w, 0.f));
        o1.x = to_tf32(fmaxf(o1.x, 0.f)); o1.y = to_tf32(fmaxf(o1.y, 0.f));
        o1.z = to_tf32(fmaxf(o1.z, 0.f)); o1.w = to_tf32(fmaxf(o1.w, 0.f));
    }

    float4* y4 = reinterpret_cast<float4*>(Y + (size_t)row * HD);
    y4[lane] = o0; y4[lane + 32] = o1;
}

// ---------------------------------------------------------------------------
// Host launch
// ---------------------------------------------------------------------------
extern "C" void kernel_launch(void* const* d_in, const int* in_sizes, int n_in,
                              void* d_out, int out_size)
{
    (void)in_sizes; (void)n_in; (void)out_size;
    const float* feats   = (const float*)d_in[0];
    const float* masks   = (const float*)d_in[1];
    const float* qw      = (const float*)d_in[2];
    const float* qbias   = (const float*)d_in[3];
    const float* kw      = (const float*)d_in[4];
    const float* kbias   = (const float*)d_in[5];
    const float* vw      = (const float*)d_in[6];
    const float* vbias   = (const float*)d_in[7];
    const float* alng    = (const float*)d_in[8];
    const float* alnb    = (const float*)d_in[9];
    const float* caw     = (const float*)d_in[10];
    const float* cabias  = (const float*)d_in[11];
    const float* calng   = (const float*)d_in[12];
    const float* calnb   = (const float*)d_in[13];
    const float* lw      = (const float*)d_in[14];
    const float* lbias   = (const float*)d_in[15];
    const float* llng    = (const float*)d_in[16];
    const float* llnb    = (const float*)d_in[17];
    float* out = (float*)d_out;

    float *Ap, *V, *O, *X1, *T1, *T2, *F, *P, *WR, *Wt, *UV, *Cv, *G, *H, *Z;
    __nv_bfloat16 *VTh, *Sh;
    cudaGetSymbolAddress((void**)&Ap, g_A);
    cudaGetSymbolAddress((void**)&V,  g_V);
    cudaGetSymbolAddress((void**)&VTh, g_VTh);
    cudaGetSymbolAddress((void**)&O,  g_O);
    cudaGetSymbolAddress((void**)&X1, g_X1);
    cudaGetSymbolAddress((void**)&T1, g_T1);
    cudaGetSymbolAddress((void**)&T2, g_T2);
    cudaGetSymbolAddress((void**)&F,  g_F);
    cudaGetSymbolAddress((void**)&Sh, g_Sh);
    cudaGetSymbolAddress((void**)&P,  g_P);
    cudaGetSymbolAddress((void**)&WR, g_WR);
    cudaGetSymbolAddress((void**)&Wt, g_Wt);
    cudaGetSymbolAddress((void**)&UV, g_UV);
    cudaGetSymbolAddress((void**)&Cv, g_Cv);
    cudaGetSymbolAddress((void**)&G,  g_G);
    cudaGetSymbolAddress((void**)&H,  g_H);
    cudaGetSymbolAddress((void**)&Z,  g_zero);

    cudaFuncSetAttribute(gemm_k<0>, cudaFuncAttributeMaxDynamicSharedMemorySize, GEMM_SMEM);
    cudaFuncSetAttribute(gemm_k<1>, cudaFuncAttributeMaxDynamicSharedMemorySize, GEMM_SMEM);
    cudaFuncSetAttribute(pv_k,      cudaFuncAttributeMaxDynamicSharedMemorySize, PV_SMEM);
    cudaFuncSetAttribute(proj3_k,   cudaFuncAttributeMaxDynamicSharedMemorySize, PROJ_SMEM);

    float* vwR = WR + 0 * (size_t)WN;
    float* cwR = WR + 1 * (size_t)WN;
    float* lwR = WR + 2 * (size_t)WN;

    const dim3 blk(256);
    round4_k<<<dim3(3 * WB + FB), blk>>>(vw, caw, lw, feats, vwR, cwR, lwR, F);
    prep_k<<<dim3(775), blk>>>(qw, kw, qbias, kbias, Wt, UV, Cv);

    const dim3 gProj(HD / BN, MTOT / BM, 1);           // (2, 256) for T1
    const dim3 gProj3(6, MTOT / BM, 1);                // (6, 256) A'/V/T2
    const dim3 gScore(SEQ / BN, SEQ / BM, BATCH);      // (8, 8, 32)
    const dim3 gPV(HD / BN, SEQ / BM, BATCH);          // (2, 8, 32)
    const dim3 gTr(SEQ / 32, HD / 32, BATCH);

    for (int i = 0; i < 3; i++) {
        const size_t wOff = (size_t)i * HD * HD;
        const size_t bOff = (size_t)i * HD;

        proj3_k<<<gProj3, blk, PROJ_SMEM>>>(F,
                                 Wt + wOff, vwR + wOff, lwR + wOff,
                                 vbias + bOff, lbias + bOff,
                                 Ap, V, T2,
                                 UV + (size_t)i * 2 * HD, G, H, Z);

        transpose_k<<<gTr, blk>>>(V, VTh);

        // scores: A = A', B = F (per-batch slice); rank-1 bias terms + mask
        gemm_k<1><<<gScore, blk, GEMM_SMEM>>>(Ap, F, masks, (float*)Sh,
                                   HD, HD, HD, SEQ,
                                   (size_t)SEQ * HD, (size_t)SEQ * HD,
                                   (size_t)SEQ * SEQ, SEQ, P, 0,
                                   G, H, Cv + i);

        pv_k<<<gPV, blk, PV_SMEM>>>(Sh, VTh, P, O);

        relu_ln_k<<<MTOT / 8, blk>>>(O, alng + bOff, alnb + bOff, X1);

        gemm_k<0><<<gProj, blk, GEMM_SMEM>>>(X1, cwR + wOff, cabias + bOff, T1,
                                  HD, HD, HD, HD, 0, 0, 0, 0, nullptr, 0,
                                  nullptr, nullptr, nullptr);

        dual_ln_add_k<<<MTOT / 8, blk>>>(T1, T2,
                                         calng + bOff, calnb + bOff,
                                         llng + bOff, llnb + bOff,
                                         (i == 2) ? out : F, (i < 2) ? 1 : 0);
    }
}